// round 1
// baseline (speedup 1.0000x reference)
#include <cuda_runtime.h>
#include <cuda_bf16.h>
#include <cstdint>

// Problem constants
#define B_  4
#define N_  2048
#define C_  768
#define H_  8
#define D_  96          // head dim
#define D3_ 32
#define TOK (B_*N_)     // 8192

// Scratch (device globals — allocation-free rule)
__device__ float g_qk[TOK * C_];   // qk = q = k projection
__device__ float g_v [TOK * C_];   // v projection
__device__ float g_s [TOK * C_];   // out1 + x_ca (pre-Wo sum)

// ---------------------------------------------------------------------------
// GEMM: Y[M, Nout] = alpha * (X[M,K] @ W[Nout,K]^T) + bias[Nout]
// Block tile 64x64, BK=16, 256 threads, 4x4 micro-tile.
// ---------------------------------------------------------------------------
__global__ __launch_bounds__(256) void gemm_bias_kernel(
    const float* __restrict__ X, const float* __restrict__ W,
    const float* __restrict__ bias, float* __restrict__ Y,
    int M, int Nout, int K, float alpha)
{
    __shared__ float Xs[16][68];   // [k][m]
    __shared__ float Ws[16][68];   // [k][n]

    const int tid = threadIdx.x;
    const int tx = tid & 15;        // 0..15
    const int ty = tid >> 4;        // 0..15
    const int m0 = blockIdx.y * 64;
    const int n0 = blockIdx.x * 64;

    float acc[4][4];
#pragma unroll
    for (int i = 0; i < 4; i++)
#pragma unroll
        for (int j = 0; j < 4; j++) acc[i][j] = 0.f;

    for (int k0 = 0; k0 < K; k0 += 16) {
#pragma unroll
        for (int i = 0; i < 4; i++) {
            int r = ty + i * 16;
            Xs[tx][r] = X[(size_t)(m0 + r) * K + k0 + tx];
            Ws[tx][r] = W[(size_t)(n0 + r) * K + k0 + tx];
        }
        __syncthreads();
#pragma unroll
        for (int kk = 0; kk < 16; kk++) {
            float4 a = *(const float4*)&Xs[kk][ty * 4];
            float4 b = *(const float4*)&Ws[kk][tx * 4];
            float av[4] = {a.x, a.y, a.z, a.w};
            float bv[4] = {b.x, b.y, b.z, b.w};
#pragma unroll
            for (int i = 0; i < 4; i++)
#pragma unroll
                for (int j = 0; j < 4; j++)
                    acc[i][j] = fmaf(av[i], bv[j], acc[i][j]);
        }
        __syncthreads();
    }

    const int nb = n0 + tx * 4;
    float4 bia = *(const float4*)&bias[nb];
#pragma unroll
    for (int i = 0; i < 4; i++) {
        int m = m0 + ty * 4 + i;
        float4 o;
        o.x = alpha * acc[i][0] + bia.x;
        o.y = alpha * acc[i][1] + bia.y;
        o.z = alpha * acc[i][2] + bia.z;
        o.w = alpha * acc[i][3] + bia.w;
        *(float4*)&Y[(size_t)m * Nout + nb] = o;
    }
}

// ---------------------------------------------------------------------------
// Flash attention (branch 1), fp32. q == k == g_qk, v == g_v.
// Grid: (N/64, B*H). Block: 256 threads. 4 lanes per query row; each lane
// owns 24 of the 96 head dims. Online softmax. Writes out1 into g_s.
// Dynamic smem: Ks[64*100] + Vs[64*100] + S[64*68] = 68608 bytes.
// ---------------------------------------------------------------------------
__global__ __launch_bounds__(256) void attn_kernel()
{
    extern __shared__ float sm[];
    float* Ks = sm;             // 64 x 100
    float* Vs = sm + 6400;      // 64 x 100
    float* Sp = sm + 12800;     // 64 x 68

    const int tid = threadIdx.x;
    const int row = tid >> 2;
    const int quarter = tid & 3;
    const int off = quarter * 24;

    const int bh = blockIdx.y;
    const int b  = bh >> 3;
    const int h  = bh & 7;
    const int q0 = blockIdx.x * 64;
    const float scale = 0.10206207261596575f; // 1/sqrt(96)

    // Load this thread's 24 q values
    const float* qptr = g_qk + ((size_t)(b * N_ + q0 + row) * H_ + h) * D_ + off;
    float q[24];
#pragma unroll
    for (int j = 0; j < 6; j++) {
        float4 t = *(const float4*)(qptr + j * 4);
        q[j*4+0] = t.x; q[j*4+1] = t.y; q[j*4+2] = t.z; q[j*4+3] = t.w;
    }

    float o[24];
#pragma unroll
    for (int j = 0; j < 24; j++) o[j] = 0.f;
    float mrow = -1e30f, l = 0.f;

    for (int kt = 0; kt < N_ / 64; kt++) {
        __syncthreads();  // protect Ks/Vs/Sp reuse from previous iteration
        const int kbase = kt * 64;
        for (int i = tid; i < 64 * 24; i += 256) {
            int r = i / 24, c = i % 24;
            size_t g = ((size_t)(b * N_ + kbase + r) * H_ + h) * D_ + c * 4;
            *(float4*)&Ks[r * 100 + c * 4] = *(const float4*)(g_qk + g);
            *(float4*)&Vs[r * 100 + c * 4] = *(const float4*)(g_v + g);
        }
        __syncthreads();

        // scores: each lane computes partial dot over its 24 dims; butterfly sum
        float tmax = -1e30f;
        float pk[16];
#pragma unroll 4
        for (int k = 0; k < 64; k++) {
            const float* kr = &Ks[k * 100 + off];
            float s = 0.f;
#pragma unroll
            for (int j = 0; j < 6; j++) {
                float4 t = *(const float4*)(kr + j * 4);
                s = fmaf(q[j*4+0], t.x, s);
                s = fmaf(q[j*4+1], t.y, s);
                s = fmaf(q[j*4+2], t.z, s);
                s = fmaf(q[j*4+3], t.w, s);
            }
            s += __shfl_xor_sync(0xffffffffu, s, 1);
            s += __shfl_xor_sync(0xffffffffu, s, 2);
            s *= scale;
            tmax = fmaxf(tmax, s);
            if ((k & 3) == quarter) pk[k >> 2] = s;
        }

        float mnew = fmaxf(mrow, tmax);
        float corr = __expf(mrow - mnew);
        float psum = 0.f;
#pragma unroll
        for (int i = 0; i < 16; i++) {
            pk[i] = __expf(pk[i] - mnew);
            psum += pk[i];
        }
        psum += __shfl_xor_sync(0xffffffffu, psum, 1);
        psum += __shfl_xor_sync(0xffffffffu, psum, 2);
        l = l * corr + psum;
        mrow = mnew;

#pragma unroll
        for (int i = 0; i < 16; i++) Sp[row * 68 + i * 4 + quarter] = pk[i];
#pragma unroll
        for (int j = 0; j < 24; j++) o[j] *= corr;
        __syncthreads();

        // o += P @ V  (this lane's 24 dims)
#pragma unroll 2
        for (int k = 0; k < 64; k++) {
            float p = Sp[row * 68 + k];
            const float* vr = &Vs[k * 100 + off];
#pragma unroll
            for (int j = 0; j < 6; j++) {
                float4 t = *(const float4*)(vr + j * 4);
                o[j*4+0] = fmaf(p, t.x, o[j*4+0]);
                o[j*4+1] = fmaf(p, t.y, o[j*4+1]);
                o[j*4+2] = fmaf(p, t.z, o[j*4+2]);
                o[j*4+3] = fmaf(p, t.w, o[j*4+3]);
            }
        }
    }

    const float inv = 1.f / l;
    float* optr = g_s + ((size_t)(b * N_ + q0 + row) * H_ + h) * D_ + off;
#pragma unroll
    for (int j = 0; j < 6; j++) {
        float4 t;
        t.x = o[j*4+0] * inv; t.y = o[j*4+1] * inv;
        t.z = o[j*4+2] * inv; t.w = o[j*4+3] * inv;
        *(float4*)(optr + j * 4) = t;
    }
}

// ---------------------------------------------------------------------------
// Branch 2: per-token projected channel attention. One block (128 thr) per
// token. Adds x_ca into g_s (which already holds out1).
// ---------------------------------------------------------------------------
__global__ __launch_bounds__(128) void branch2_kernel(
    const float* __restrict__ We, const float* __restrict__ be,
    const float* __restrict__ Wf, const float* __restrict__ bf)
{
    __shared__ float sQ[768];
    __shared__ float sV[768];
    __shared__ float sKp[256];   // [e*8 + h]
    __shared__ float sVp[256];   // [h*32 + e]
    __shared__ float sA[32 * 96];

    const int t = threadIdx.x;
    const size_t tok = blockIdx.x;
    const float* qrow = g_qk + tok * C_;
    const float* vrow = g_v  + tok * C_;

    for (int i = t; i < 192; i += 128) {
        ((float4*)sQ)[i] = ((const float4*)qrow)[i];
        ((float4*)sV)[i] = ((const float4*)vrow)[i];
    }
    __syncthreads();

    // k_proj[h][e], v_proj[h][e]
    for (int p = t; p < 256; p += 128) {
        int h = p >> 5, e = p & 31;
        float accK = be[e], accV = bf[e];
        const float* wK = We + e * 96;
        const float* wF = Wf + e * 96;
        const float* qh = sQ + h * 96;
        const float* vh = sV + h * 96;
#pragma unroll 8
        for (int d = 0; d < 96; d++) {
            accK = fmaf(qh[d], wK[d], accK);
            accV = fmaf(vh[d], wF[d], accV);
        }
        sKp[e * 8 + h] = accK;
        sVp[h * 32 + e] = accV;
    }
    __syncthreads();

    // A[e][d] = sum_h kp[h][e]*q[h][d], softmax over d (96). 4 lanes per e.
    {
        const int e = t >> 2, qtr = t & 3;
        float a[24];
        float amax = -1e30f;
#pragma unroll
        for (int i = 0; i < 24; i++) {
            int d = qtr * 24 + i;
            float s = 0.f;
#pragma unroll
            for (int h = 0; h < 8; h++)
                s = fmaf(sKp[e * 8 + h], sQ[h * 96 + d], s);
            a[i] = s;
            amax = fmaxf(amax, s);
        }
        amax = fmaxf(amax, __shfl_xor_sync(0xffffffffu, amax, 1));
        amax = fmaxf(amax, __shfl_xor_sync(0xffffffffu, amax, 2));
        float asum = 0.f;
#pragma unroll
        for (int i = 0; i < 24; i++) {
            a[i] = __expf(a[i] - amax);
            asum += a[i];
        }
        asum += __shfl_xor_sync(0xffffffffu, asum, 1);
        asum += __shfl_xor_sync(0xffffffffu, asum, 2);
        float ainv = 1.f / asum;
#pragma unroll
        for (int i = 0; i < 24; i++) sA[e * 96 + qtr * 24 + i] = a[i] * ainv;
    }
    __syncthreads();

    // x_ca[h][d] = sum_e vp[h][e]*A[e][d]; accumulate into g_s
    for (int p = t; p < 768; p += 128) {
        int h = p / 96, d = p % 96;
        float s = 0.f;
        const float* vp = sVp + h * 32;
#pragma unroll 8
        for (int e2 = 0; e2 < 32; e2++)
            s = fmaf(vp[e2], sA[e2 * 96 + d], s);
        g_s[tok * C_ + p] += s;
    }
}

// ---------------------------------------------------------------------------
// Launch
// ---------------------------------------------------------------------------
extern "C" void kernel_launch(void* const* d_in, const int* in_sizes, int n_in,
                              void* d_out, int out_size)
{
    const float* x   = (const float*)d_in[0];
    const float* Wqk = (const float*)d_in[1];
    const float* bqk = (const float*)d_in[2];
    const float* Wv  = (const float*)d_in[3];
    const float* bv  = (const float*)d_in[4];
    const float* Wo  = (const float*)d_in[5];
    const float* bo  = (const float*)d_in[6];
    const float* We  = (const float*)d_in[7];
    const float* be  = (const float*)d_in[8];
    const float* Wf  = (const float*)d_in[9];
    const float* bf  = (const float*)d_in[10];
    float* out = (float*)d_out;

    float *p_qk, *p_v, *p_s;
    cudaGetSymbolAddress((void**)&p_qk, g_qk);
    cudaGetSymbolAddress((void**)&p_v,  g_v);
    cudaGetSymbolAddress((void**)&p_s,  g_s);

    static const int ATTN_SMEM = (64 * 100 * 2 + 64 * 68) * 4; // 68608 B
    cudaFuncSetAttribute(attn_kernel,
                         cudaFuncAttributeMaxDynamicSharedMemorySize, ATTN_SMEM);

    dim3 gGemm(C_ / 64, TOK / 64);   // (12, 128)
    // qk and v projections
    gemm_bias_kernel<<<gGemm, 256>>>(x, Wqk, bqk, p_qk, TOK, C_, C_, 1.0f);
    gemm_bias_kernel<<<gGemm, 256>>>(x, Wv,  bv,  p_v,  TOK, C_, C_, 1.0f);

    // branch-1 flash attention -> g_s = out1
    dim3 gAttn(N_ / 64, B_ * H_);    // (32, 32)
    attn_kernel<<<gAttn, 256, ATTN_SMEM>>>();

    // branch-2 -> g_s += x_ca
    branch2_kernel<<<TOK, 128>>>(We, be, Wf, bf);

    // out = 0.5 * (g_s @ Wo^T) + bo   (single fused output projection)
    gemm_bias_kernel<<<gGemm, 256>>>(p_s, Wo, bo, out, TOK, C_, C_, 0.5f);
}

// round 4
// speedup vs baseline: 1.8584x; 1.8584x over previous
#include <cuda_runtime.h>
#include <cuda_bf16.h>
#include <cstdint>

// ===========================================================================
// Problem constants
// ===========================================================================
#define B_   4
#define N_   2048
#define C_   768
#define H_   8
#define D_   96
#define BH_  32            // B*H
#define TOK  8192          // B*N
#define DPAD 128           // head dim padded for MMA K

// ===========================================================================
// Device-global scratch (allocation-free rule)
// ===========================================================================
__device__ __align__(256) float g_qk[(size_t)BH_ * N_ * D_];   // fp32 q(=k) [bh][n][d]
__device__ __align__(256) float g_v [(size_t)BH_ * N_ * D_];   // fp32 v     [bh][n][d]
__device__ __align__(256) float g_s [(size_t)TOK * C_];        // out1 + x_ca

__device__ __align__(256) __nv_bfloat16 g_xhi[(size_t)TOK * C_],  g_xlo[(size_t)TOK * C_];
__device__ __align__(256) __nv_bfloat16 g_Wqkhi[C_*C_], g_Wqklo[C_*C_];
__device__ __align__(256) __nv_bfloat16 g_Wvhi [C_*C_], g_Wvlo [C_*C_];
__device__ __align__(256) __nv_bfloat16 g_Wohi [C_*C_], g_Wolo [C_*C_];
__device__ __align__(256) __nv_bfloat16 g_qhi [(size_t)BH_ * N_ * DPAD], g_qlo [(size_t)BH_ * N_ * DPAD];
__device__ __align__(256) __nv_bfloat16 g_vthi[(size_t)BH_ * DPAD * N_], g_vtlo[(size_t)BH_ * DPAD * N_];
__device__ __align__(256) __nv_bfloat16 g_Phi[(size_t)BH_ * N_ * N_], g_Plo[(size_t)BH_ * N_ * N_]; // S then P
__device__ __align__(256) __nv_bfloat16 g_shi[(size_t)TOK * C_], g_slo[(size_t)TOK * C_];

// ===========================================================================
// Asm helpers (all base-ISA: sm_80+, valid on plain sm_103 target)
// ===========================================================================
__device__ __forceinline__ uint32_t smem_to_u32(const void* p) {
    uint32_t a;
    asm("{ .reg .u64 t; cvta.to.shared.u64 t, %1; cvt.u32.u64 %0, t; }" : "=r"(a) : "l"(p));
    return a;
}
__device__ __forceinline__ void cp16(uint32_t s, const void* g) {
    asm volatile("cp.async.cg.shared.global [%0], [%1], 16;" :: "r"(s), "l"(g));
}
__device__ __forceinline__ void cp_commit() {
    asm volatile("cp.async.commit_group;" ::: "memory");
}
template<int NN> __device__ __forceinline__ void cp_wait() {
    asm volatile("cp.async.wait_group %0;" :: "n"(NN) : "memory");
}
__device__ __forceinline__ void ldsm4(uint32_t (&r)[4], uint32_t addr) {
    asm volatile("ldmatrix.sync.aligned.m8n8.x4.shared.b16 {%0,%1,%2,%3}, [%4];"
                 : "=r"(r[0]), "=r"(r[1]), "=r"(r[2]), "=r"(r[3]) : "r"(addr));
}
__device__ __forceinline__ void mma16816(float (&d)[4], const uint32_t (&a)[4],
                                         uint32_t b0, uint32_t b1) {
    asm volatile("mma.sync.aligned.m16n8k16.row.col.f32.bf16.bf16.f32 "
                 "{%0,%1,%2,%3}, {%4,%5,%6,%7}, {%8,%9}, {%0,%1,%2,%3};"
                 : "+f"(d[0]), "+f"(d[1]), "+f"(d[2]), "+f"(d[3])
                 : "r"(a[0]), "r"(a[1]), "r"(a[2]), "r"(a[3]), "r"(b0), "r"(b1));
}

// ===========================================================================
// Split fp32 -> bf16 hi + bf16 lo
// ===========================================================================
__global__ void split_kernel(const float* __restrict__ src,
                             __nv_bfloat16* __restrict__ hi,
                             __nv_bfloat16* __restrict__ lo, int n)
{
    int i = blockIdx.x * blockDim.x + threadIdx.x;
    if (i < n) {
        float v = src[i];
        __nv_bfloat16 h = __float2bfloat16(v);
        hi[i] = h;
        lo[i] = __float2bfloat16(v - __bfloat162float(h));
    }
}

// ===========================================================================
// HMMA split-bf16 GEMM: D[128x64 tile] = A @ B^T (both K-major)
// 256 threads = 8 warps (2 m x 4 n), warp tile 64x16, BK=32, double buffer.
// D = Ahi*Bhi + Ahi*Blo + Alo*Bhi (fp32 accum).
// MODE: 0 proj-qk, 1 proj-v, 2 scores->S(hi/lo), 3 PV->g_s, 4 out-proj
// ===========================================================================
#define ROWB   80         // bytes per smem row: 32 bf16 + 8 pad
#define SA_HI  0
#define SA_LO  10240
#define SB_HI  20480
#define SB_LO  25600
#define STAGE_B 30720
#define GEMM_SMEM (2 * STAGE_B)

template<int MODE>
__global__ __launch_bounds__(256, 2) void mma_gemm(
    const __nv_bfloat16* __restrict__ Ahi_, const __nv_bfloat16* __restrict__ Alo_,
    const __nv_bfloat16* __restrict__ Bhi_, const __nv_bfloat16* __restrict__ Blo_,
    const float* __restrict__ bias, float* __restrict__ outp,
    int K, int lda, int ldb)
{
    extern __shared__ __align__(128) char sm[];
    const uint32_t sbase = smem_to_u32(sm);
    const int tid  = threadIdx.x;
    const int wid  = tid >> 5, lane = tid & 31;
    const int warp_m = wid >> 2, warp_n = wid & 3;

    const int m0 = blockIdx.x * 128;
    const int n0 = blockIdx.y * 64;
    const int bh = blockIdx.z;

    const __nv_bfloat16 *Ahi = Ahi_, *Alo = Alo_, *Bhi = Bhi_, *Blo = Blo_;
    if (MODE == 2) {
        size_t o = (size_t)bh * N_ * DPAD;
        Ahi += o; Alo += o; Bhi += o; Blo += o;
    } else if (MODE == 3) {
        size_t oa = (size_t)bh * N_ * N_;
        size_t ob = (size_t)bh * DPAD * N_;
        Ahi += oa; Alo += oa; Bhi += ob; Blo += ob;
    }

    // load assignments
    const int ar  = tid >> 2;           // A row (0..63; +64 for part 1)
    const int acb = (tid & 3) * 16;     // byte col offset within 64B row (16B chunks)
    const int ace = (tid & 3) * 8;      // element col offset

    auto issue = [&](int it) {
        const uint32_t sb = sbase + (uint32_t)(it & 1) * STAGE_B;
        const int k0 = it * 32;
#pragma unroll
        for (int p = 0; p < 2; ++p) {
            const int r = ar + p * 64;
            const size_t go = (size_t)(m0 + r) * lda + k0 + ace;
            const uint32_t so = sb + (uint32_t)(r * ROWB) + acb;
            cp16(so + SA_HI, Ahi + go);
            cp16(so + SA_LO, Alo + go);
        }
        {
            const size_t go = (size_t)(n0 + ar) * ldb + k0 + ace;
            const uint32_t so = sb + (uint32_t)(ar * ROWB) + acb;
            cp16(so + SB_HI, Bhi + go);
            cp16(so + SB_LO, Blo + go);
        }
        cp_commit();
    };

    float acc[4][2][4];
#pragma unroll
    for (int i = 0; i < 4; i++)
#pragma unroll
        for (int j = 0; j < 2; j++)
#pragma unroll
            for (int e = 0; e < 4; e++) acc[i][j][e] = 0.f;

    const int nIter = K >> 5;
    issue(0);

    const uint32_t lrow = (uint32_t)(lane & 15);
    const uint32_t lhalf = (uint32_t)(lane >> 4);

    for (int it = 0; it < nIter; ++it) {
        if (it + 1 < nIter) { issue(it + 1); cp_wait<1>(); }
        else                { cp_wait<0>(); }
        __syncthreads();
        const uint32_t sb = sbase + (uint32_t)(it & 1) * STAGE_B;
#pragma unroll
        for (int ks = 0; ks < 2; ++ks) {
            const uint32_t kb = (uint32_t)(ks * 32);
            uint32_t bH[4], bL[4];
            {
                const uint32_t bd = sb + SB_HI + (warp_n * 16 + lrow) * ROWB + lhalf * 16 + kb;
                ldsm4(bH, bd);
                ldsm4(bL, bd + (SB_LO - SB_HI));
            }
            uint32_t aH[4][4], aL[4][4];
#pragma unroll
            for (int i = 0; i < 4; ++i) {
                const uint32_t ad = sb + SA_HI + (warp_m * 64 + i * 16 + lrow) * ROWB + lhalf * 16 + kb;
                ldsm4(aH[i], ad);
                ldsm4(aL[i], ad + (SA_LO - SA_HI));
            }
#pragma unroll
            for (int i = 0; i < 4; ++i) {
#pragma unroll
                for (int j = 0; j < 2; ++j) {
                    const uint32_t b0h = (j == 0) ? bH[0] : bH[1];
                    const uint32_t b1h = (j == 0) ? bH[2] : bH[3];
                    const uint32_t b0l = (j == 0) ? bL[0] : bL[1];
                    const uint32_t b1l = (j == 0) ? bL[2] : bL[3];
                    mma16816(acc[i][j], aH[i], b0h, b1h);
                    mma16816(acc[i][j], aH[i], b0l, b1l);
                    mma16816(acc[i][j], aL[i], b0h, b1h);
                }
            }
        }
        __syncthreads();
    }

    // ---------------- epilogue ----------------
    const int grp = lane >> 2, t4 = lane & 3;
#pragma unroll
    for (int i = 0; i < 4; ++i) {
#pragma unroll
        for (int j = 0; j < 2; ++j) {
#pragma unroll
            for (int e = 0; e < 4; ++e) {
                const int m = m0 + warp_m * 64 + i * 16 + grp + (e >> 1) * 8;
                const int n = n0 + warp_n * 16 + j * 8 + t4 * 2 + (e & 1);
                float r = acc[i][j][e];
                if (MODE == 0 || MODE == 1) {
                    r += bias[n];
                    const int b = m >> 11, ntok = m & 2047;
                    const int h = n / 96, d = n - h * 96;
                    const int bhh = b * 8 + h;
                    __nv_bfloat16 hi = __float2bfloat16(r);
                    __nv_bfloat16 lo = __float2bfloat16(r - __bfloat162float(hi));
                    if (MODE == 0) {
                        g_qk[((size_t)bhh * N_ + ntok) * D_ + d] = r;
                        const size_t qo = ((size_t)bhh * N_ + ntok) * DPAD + d;
                        g_qhi[qo] = hi; g_qlo[qo] = lo;
                    } else {
                        g_v[((size_t)bhh * N_ + ntok) * D_ + d] = r;
                        const size_t vo = ((size_t)bhh * DPAD + d) * N_ + ntok;
                        g_vthi[vo] = hi; g_vtlo[vo] = lo;
                    }
                } else if (MODE == 2) {
                    r *= 0.10206207261596575f;   // 1/sqrt(96)
                    __nv_bfloat16 hi = __float2bfloat16(r);
                    __nv_bfloat16 lo = __float2bfloat16(r - __bfloat162float(hi));
                    const size_t o = ((size_t)bh * N_ + m) * N_ + n;
                    g_Phi[o] = hi; g_Plo[o] = lo;
                } else if (MODE == 3) {
                    if (n < D_) {
                        const int b = bh >> 3, h = bh & 7;
                        g_s[(size_t)(b * N_ + m) * C_ + h * D_ + n] = r;
                    }
                } else {
                    outp[(size_t)m * C_ + n] = 0.5f * r + bias[n];
                }
            }
        }
    }
}

// ===========================================================================
// Row softmax in place over (g_Phi,g_Plo): S = hi+lo -> P, re-split.
// One block per row of 2048.
// ===========================================================================
__global__ __launch_bounds__(256) void softmax_kernel()
{
    __shared__ float red[8];
    const size_t row = blockIdx.x;
    const int t = threadIdx.x, lane = t & 31, w = t >> 5;

    __nv_bfloat16* ph = g_Phi + row * N_ + t * 8;
    __nv_bfloat16* pl = g_Plo + row * N_ + t * 8;
    __nv_bfloat16 hb[8], lb[8];
    *(uint4*)hb = *(const uint4*)ph;
    *(uint4*)lb = *(const uint4*)pl;

    float v[8];
#pragma unroll
    for (int i = 0; i < 8; i++)
        v[i] = __bfloat162float(hb[i]) + __bfloat162float(lb[i]);

    float mx = v[0];
#pragma unroll
    for (int i = 1; i < 8; i++) mx = fmaxf(mx, v[i]);
#pragma unroll
    for (int s = 16; s > 0; s >>= 1) mx = fmaxf(mx, __shfl_xor_sync(0xffffffffu, mx, s));
    if (lane == 0) red[w] = mx;
    __syncthreads();
    if (w == 0) {
        float m2 = (lane < 8) ? red[lane] : -1e30f;
#pragma unroll
        for (int s = 4; s > 0; s >>= 1) m2 = fmaxf(m2, __shfl_xor_sync(0xffffffffu, m2, s));
        if (lane == 0) red[0] = m2;
    }
    __syncthreads();
    const float rowmax = red[0];

    float sum = 0.f;
#pragma unroll
    for (int i = 0; i < 8; i++) { v[i] = __expf(v[i] - rowmax); sum += v[i]; }
#pragma unroll
    for (int s = 16; s > 0; s >>= 1) sum += __shfl_xor_sync(0xffffffffu, sum, s);
    __syncthreads();
    if (lane == 0) red[w] = sum;
    __syncthreads();
    if (w == 0) {
        float s2 = (lane < 8) ? red[lane] : 0.f;
#pragma unroll
        for (int s = 4; s > 0; s >>= 1) s2 += __shfl_xor_sync(0xffffffffu, s2, s);
        if (lane == 0) red[0] = s2;
    }
    __syncthreads();
    const float inv = 1.f / red[0];

#pragma unroll
    for (int i = 0; i < 8; i++) {
        const float p = v[i] * inv;
        __nv_bfloat16 hi = __float2bfloat16(p);
        hb[i] = hi;
        lb[i] = __float2bfloat16(p - __bfloat162float(hi));
    }
    *(uint4*)ph = *(const uint4*)hb;
    *(uint4*)pl = *(const uint4*)lb;
}

// ===========================================================================
// Branch 2: per-token projected channel attention; g_s += x_ca
// ===========================================================================
__global__ __launch_bounds__(128) void branch2_kernel(
    const float* __restrict__ We, const float* __restrict__ be,
    const float* __restrict__ Wf, const float* __restrict__ bf)
{
    __shared__ float sQ[768];
    __shared__ float sV[768];
    __shared__ float sKp[256];   // [e*8 + h]
    __shared__ float sVp[256];   // [h*32 + e]
    __shared__ float sA[32 * 96];

    const int t = threadIdx.x;
    const size_t tok = blockIdx.x;
    const int b = (int)(tok >> 11), ntok = (int)(tok & 2047);

    for (int i = t; i < 192; i += 128) {
        const int i4 = i * 4;
        const int h = i4 / 96, d = i4 - h * 96;
        const size_t off = ((size_t)(b * 8 + h) * N_ + ntok) * D_ + d;
        ((float4*)sQ)[i] = *(const float4*)(g_qk + off);
        ((float4*)sV)[i] = *(const float4*)(g_v + off);
    }
    __syncthreads();

    for (int p = t; p < 256; p += 128) {
        const int h = p >> 5, e = p & 31;
        float accK = be[e], accV = bf[e];
        const float* wK = We + e * 96;
        const float* wF = Wf + e * 96;
        const float* qh = sQ + h * 96;
        const float* vh = sV + h * 96;
#pragma unroll 8
        for (int d = 0; d < 96; d++) {
            accK = fmaf(qh[d], wK[d], accK);
            accV = fmaf(vh[d], wF[d], accV);
        }
        sKp[e * 8 + h] = accK;
        sVp[h * 32 + e] = accV;
    }
    __syncthreads();

    {
        const int e = t >> 2, qtr = t & 3;
        float a[24];
        float amax = -1e30f;
#pragma unroll
        for (int i = 0; i < 24; i++) {
            const int d = qtr * 24 + i;
            float s = 0.f;
#pragma unroll
            for (int h = 0; h < 8; h++)
                s = fmaf(sKp[e * 8 + h], sQ[h * 96 + d], s);
            a[i] = s;
            amax = fmaxf(amax, s);
        }
        amax = fmaxf(amax, __shfl_xor_sync(0xffffffffu, amax, 1));
        amax = fmaxf(amax, __shfl_xor_sync(0xffffffffu, amax, 2));
        float asum = 0.f;
#pragma unroll
        for (int i = 0; i < 24; i++) { a[i] = __expf(a[i] - amax); asum += a[i]; }
        asum += __shfl_xor_sync(0xffffffffu, asum, 1);
        asum += __shfl_xor_sync(0xffffffffu, asum, 2);
        const float ainv = 1.f / asum;
#pragma unroll
        for (int i = 0; i < 24; i++) sA[e * 96 + qtr * 24 + i] = a[i] * ainv;
    }
    __syncthreads();

    for (int p = t; p < 768; p += 128) {
        const int h = p / 96, d = p - h * 96;
        float s = 0.f;
        const float* vp = sVp + h * 32;
#pragma unroll 8
        for (int e2 = 0; e2 < 32; e2++)
            s = fmaf(vp[e2], sA[e2 * 96 + d], s);
        g_s[tok * C_ + p] += s;
    }
}

// ===========================================================================
// Launch
// ===========================================================================
extern "C" void kernel_launch(void* const* d_in, const int* in_sizes, int n_in,
                              void* d_out, int out_size)
{
    const float* x   = (const float*)d_in[0];
    const float* Wqk = (const float*)d_in[1];
    const float* bqk = (const float*)d_in[2];
    const float* Wv  = (const float*)d_in[3];
    const float* bv  = (const float*)d_in[4];
    const float* Wo  = (const float*)d_in[5];
    const float* bo  = (const float*)d_in[6];
    const float* We  = (const float*)d_in[7];
    const float* be  = (const float*)d_in[8];
    const float* Wf  = (const float*)d_in[9];
    const float* bf  = (const float*)d_in[10];
    float* out = (float*)d_out;

    void *p_xhi, *p_xlo, *p_wqkhi, *p_wqklo, *p_wvhi, *p_wvlo, *p_wohi, *p_wolo;
    void *p_qhi, *p_qlo, *p_vthi, *p_vtlo, *p_phi, *p_plo, *p_shi, *p_slo, *p_s;
    cudaGetSymbolAddress(&p_xhi, g_xhi);     cudaGetSymbolAddress(&p_xlo, g_xlo);
    cudaGetSymbolAddress(&p_wqkhi, g_Wqkhi); cudaGetSymbolAddress(&p_wqklo, g_Wqklo);
    cudaGetSymbolAddress(&p_wvhi, g_Wvhi);   cudaGetSymbolAddress(&p_wvlo, g_Wvlo);
    cudaGetSymbolAddress(&p_wohi, g_Wohi);   cudaGetSymbolAddress(&p_wolo, g_Wolo);
    cudaGetSymbolAddress(&p_qhi, g_qhi);     cudaGetSymbolAddress(&p_qlo, g_qlo);
    cudaGetSymbolAddress(&p_vthi, g_vthi);   cudaGetSymbolAddress(&p_vtlo, g_vtlo);
    cudaGetSymbolAddress(&p_phi, g_Phi);     cudaGetSymbolAddress(&p_plo, g_Plo);
    cudaGetSymbolAddress(&p_shi, g_shi);     cudaGetSymbolAddress(&p_slo, g_slo);
    cudaGetSymbolAddress(&p_s, g_s);

    cudaFuncSetAttribute(mma_gemm<0>, cudaFuncAttributeMaxDynamicSharedMemorySize, GEMM_SMEM);
    cudaFuncSetAttribute(mma_gemm<1>, cudaFuncAttributeMaxDynamicSharedMemorySize, GEMM_SMEM);
    cudaFuncSetAttribute(mma_gemm<2>, cudaFuncAttributeMaxDynamicSharedMemorySize, GEMM_SMEM);
    cudaFuncSetAttribute(mma_gemm<3>, cudaFuncAttributeMaxDynamicSharedMemorySize, GEMM_SMEM);
    cudaFuncSetAttribute(mma_gemm<4>, cudaFuncAttributeMaxDynamicSharedMemorySize, GEMM_SMEM);

    // 1) hi/lo splits of x and weights
    {
        const int n = TOK * C_;
        split_kernel<<<(n + 255) / 256, 256>>>(x, (__nv_bfloat16*)p_xhi, (__nv_bfloat16*)p_xlo, n);
        const int nw = C_ * C_;
        split_kernel<<<(nw + 255) / 256, 256>>>(Wqk, (__nv_bfloat16*)p_wqkhi, (__nv_bfloat16*)p_wqklo, nw);
        split_kernel<<<(nw + 255) / 256, 256>>>(Wv,  (__nv_bfloat16*)p_wvhi,  (__nv_bfloat16*)p_wvlo,  nw);
        split_kernel<<<(nw + 255) / 256, 256>>>(Wo,  (__nv_bfloat16*)p_wohi,  (__nv_bfloat16*)p_wolo,  nw);
    }

    // 2) zero the padded q / vt arrays (dims 96..127 must be 0 for K-padding)
    const size_t qbytes = (size_t)BH_ * N_ * DPAD * sizeof(__nv_bfloat16);
    cudaMemsetAsync(p_qhi, 0, qbytes);
    cudaMemsetAsync(p_qlo, 0, qbytes);
    cudaMemsetAsync(p_vthi, 0, qbytes);
    cudaMemsetAsync(p_vtlo, 0, qbytes);

    // 3) projections (M=8192, N=768, K=768)
    dim3 gProj(TOK / 128, C_ / 64);
    mma_gemm<0><<<gProj, 256, GEMM_SMEM>>>(
        (const __nv_bfloat16*)p_xhi, (const __nv_bfloat16*)p_xlo,
        (const __nv_bfloat16*)p_wqkhi, (const __nv_bfloat16*)p_wqklo,
        bqk, nullptr, C_, C_, C_);
    mma_gemm<1><<<gProj, 256, GEMM_SMEM>>>(
        (const __nv_bfloat16*)p_xhi, (const __nv_bfloat16*)p_xlo,
        (const __nv_bfloat16*)p_wvhi, (const __nv_bfloat16*)p_wvlo,
        bv, nullptr, C_, C_, C_);

    // 4) scores S = scale * q q^T  (per bh: M=N=2048, K=128) -> Phi/Plo
    dim3 gScores(N_ / 128, N_ / 64, BH_);
    mma_gemm<2><<<gScores, 256, GEMM_SMEM>>>(
        (const __nv_bfloat16*)p_qhi, (const __nv_bfloat16*)p_qlo,
        (const __nv_bfloat16*)p_qhi, (const __nv_bfloat16*)p_qlo,
        nullptr, nullptr, DPAD, DPAD, DPAD);

    // 5) softmax in place on (Phi,Plo)
    softmax_kernel<<<BH_ * N_, 256>>>();

    // 6) out1 = P V  (per bh: M=2048, N=128 pad, K=2048) -> g_s
    dim3 gPV(N_ / 128, DPAD / 64, BH_);
    mma_gemm<3><<<gPV, 256, GEMM_SMEM>>>(
        (const __nv_bfloat16*)p_phi, (const __nv_bfloat16*)p_plo,
        (const __nv_bfloat16*)p_vthi, (const __nv_bfloat16*)p_vtlo,
        nullptr, nullptr, N_, N_, N_);

    // 7) branch 2: g_s += x_ca
    branch2_kernel<<<TOK, 128>>>(We, be, Wf, bf);

    // 8) split s, then out = 0.5*(s @ Wo^T) + bo
    {
        const int n = TOK * C_;
        split_kernel<<<(n + 255) / 256, 256>>>((const float*)p_s,
                                               (__nv_bfloat16*)p_shi, (__nv_bfloat16*)p_slo, n);
    }
    mma_gemm<4><<<gProj, 256, GEMM_SMEM>>>(
        (const __nv_bfloat16*)p_shi, (const __nv_bfloat16*)p_slo,
        (const __nv_bfloat16*)p_wohi, (const __nv_bfloat16*)p_wolo,
        bo, out, C_, C_, C_);
}

// round 6
// speedup vs baseline: 2.2420x; 1.2064x over previous
#include <cuda_runtime.h>
#include <cuda_bf16.h>
#include <cstdint>

// R6 = R5 re-bench: R5 failed with cudaErrorSystemNotReady (802) in harness
// init, before any kernel ran — infra flake, not kernel content.

// ===========================================================================
// Problem constants
// ===========================================================================
#define B_   4
#define N_   2048
#define C_   768
#define H_   8
#define D_   96
#define BH_  32            // B*H
#define TOK  8192          // B*N
#define DPAD 128           // head dim padded (stride for q arrays)

// ===========================================================================
// Device-global scratch (allocation-free rule)
// ===========================================================================
__device__ __align__(256) float g_qk[(size_t)BH_ * N_ * D_];   // fp32 q(=k) [bh][n][d]
__device__ __align__(256) float g_v [(size_t)BH_ * N_ * D_];   // fp32 v     [bh][n][d]
__device__ __align__(256) float g_s [(size_t)TOK * C_];        // out1 + x_ca

__device__ __align__(256) __nv_bfloat16 g_xhi[(size_t)TOK * C_],  g_xlo[(size_t)TOK * C_];
__device__ __align__(256) __nv_bfloat16 g_Wqkhi[C_*C_], g_Wqklo[C_*C_];
__device__ __align__(256) __nv_bfloat16 g_Wvhi [C_*C_], g_Wvlo [C_*C_];
__device__ __align__(256) __nv_bfloat16 g_Wohi [C_*C_], g_Wolo [C_*C_];
__device__ __align__(256) __nv_bfloat16 g_qhi [(size_t)BH_ * N_ * DPAD], g_qlo [(size_t)BH_ * N_ * DPAD];
__device__ __align__(256) __nv_bfloat16 g_vthi[(size_t)BH_ * DPAD * N_], g_vtlo[(size_t)BH_ * DPAD * N_];
__device__ __align__(256) __nv_bfloat16 g_shi[(size_t)TOK * C_], g_slo[(size_t)TOK * C_];

// ===========================================================================
// Asm helpers (base ISA, sm_80+: valid on plain sm_103 target)
// ===========================================================================
__device__ __forceinline__ uint32_t smem_to_u32(const void* p) {
    uint32_t a;
    asm("{ .reg .u64 t; cvta.to.shared.u64 t, %1; cvt.u32.u64 %0, t; }" : "=r"(a) : "l"(p));
    return a;
}
__device__ __forceinline__ void cp16(uint32_t s, const void* g) {
    asm volatile("cp.async.cg.shared.global [%0], [%1], 16;" :: "r"(s), "l"(g));
}
__device__ __forceinline__ void cp_commit() {
    asm volatile("cp.async.commit_group;" ::: "memory");
}
template<int NN> __device__ __forceinline__ void cp_wait() {
    asm volatile("cp.async.wait_group %0;" :: "n"(NN) : "memory");
}
__device__ __forceinline__ void ldsm4(uint32_t (&r)[4], uint32_t addr) {
    asm volatile("ldmatrix.sync.aligned.m8n8.x4.shared.b16 {%0,%1,%2,%3}, [%4];"
                 : "=r"(r[0]), "=r"(r[1]), "=r"(r[2]), "=r"(r[3]) : "r"(addr));
}
__device__ __forceinline__ void mma16816(float (&d)[4], const uint32_t (&a)[4],
                                         uint32_t b0, uint32_t b1) {
    asm volatile("mma.sync.aligned.m16n8k16.row.col.f32.bf16.bf16.f32 "
                 "{%0,%1,%2,%3}, {%4,%5,%6,%7}, {%8,%9}, {%0,%1,%2,%3};"
                 : "+f"(d[0]), "+f"(d[1]), "+f"(d[2]), "+f"(d[3])
                 : "r"(a[0]), "r"(a[1]), "r"(a[2]), "r"(a[3]), "r"(b0), "r"(b1));
}
__device__ __forceinline__ float ex2f(float x) {
    float y; asm("ex2.approx.f32 %0, %1;" : "=f"(y) : "f"(x)); return y;
}
__device__ __forceinline__ void pack_split(float x, float y, uint32_t& hi, uint32_t& lo) {
    float2 v = make_float2(x, y);
    __nv_bfloat162 h = __float22bfloat162_rn(v);
    float2 r = make_float2(x - __bfloat162float(h.x), y - __bfloat162float(h.y));
    __nv_bfloat162 l = __float22bfloat162_rn(r);
    hi = *(uint32_t*)&h; lo = *(uint32_t*)&l;
}

// ===========================================================================
// Split fp32 -> bf16 hi + bf16 lo
// ===========================================================================
__global__ void split_kernel(const float* __restrict__ src,
                             __nv_bfloat16* __restrict__ hi,
                             __nv_bfloat16* __restrict__ lo, int n)
{
    int i = blockIdx.x * blockDim.x + threadIdx.x;
    if (i < n) {
        float v = src[i];
        __nv_bfloat16 h = __float2bfloat16(v);
        hi[i] = h;
        lo[i] = __float2bfloat16(v - __bfloat162float(h));
    }
}

// ===========================================================================
// HMMA split-bf16 GEMM (projections + output proj).
// MODE: 0 proj-qk, 1 proj-v, 4 out-proj
// ===========================================================================
#define ROWB   80
#define SA_HI  0
#define SA_LO  10240
#define SB_HI  20480
#define SB_LO  25600
#define STAGE_B 30720
#define GEMM_SMEM (2 * STAGE_B)

template<int MODE>
__global__ __launch_bounds__(256, 2) void mma_gemm(
    const __nv_bfloat16* __restrict__ Ahi_, const __nv_bfloat16* __restrict__ Alo_,
    const __nv_bfloat16* __restrict__ Bhi_, const __nv_bfloat16* __restrict__ Blo_,
    const float* __restrict__ bias, float* __restrict__ outp,
    int K, int lda, int ldb)
{
    extern __shared__ __align__(128) char sm[];
    const uint32_t sbase = smem_to_u32(sm);
    const int tid  = threadIdx.x;
    const int wid  = tid >> 5, lane = tid & 31;
    const int warp_m = wid >> 2, warp_n = wid & 3;

    const int m0 = blockIdx.x * 128;
    const int n0 = blockIdx.y * 64;

    const __nv_bfloat16 *Ahi = Ahi_, *Alo = Alo_, *Bhi = Bhi_, *Blo = Blo_;

    const int ar  = tid >> 2;
    const int acb = (tid & 3) * 16;
    const int ace = (tid & 3) * 8;

    auto issue = [&](int it) {
        const uint32_t sb = sbase + (uint32_t)(it & 1) * STAGE_B;
        const int k0 = it * 32;
#pragma unroll
        for (int p = 0; p < 2; ++p) {
            const int r = ar + p * 64;
            const size_t go = (size_t)(m0 + r) * lda + k0 + ace;
            const uint32_t so = sb + (uint32_t)(r * ROWB) + acb;
            cp16(so + SA_HI, Ahi + go);
            cp16(so + SA_LO, Alo + go);
        }
        {
            const size_t go = (size_t)(n0 + ar) * ldb + k0 + ace;
            const uint32_t so = sb + (uint32_t)(ar * ROWB) + acb;
            cp16(so + SB_HI, Bhi + go);
            cp16(so + SB_LO, Blo + go);
        }
        cp_commit();
    };

    float acc[4][2][4];
#pragma unroll
    for (int i = 0; i < 4; i++)
#pragma unroll
        for (int j = 0; j < 2; j++)
#pragma unroll
            for (int e = 0; e < 4; e++) acc[i][j][e] = 0.f;

    const int nIter = K >> 5;
    issue(0);

    const uint32_t lrow = (uint32_t)(lane & 15);
    const uint32_t lhalf = (uint32_t)(lane >> 4);

    for (int it = 0; it < nIter; ++it) {
        if (it + 1 < nIter) { issue(it + 1); cp_wait<1>(); }
        else                { cp_wait<0>(); }
        __syncthreads();
        const uint32_t sb = sbase + (uint32_t)(it & 1) * STAGE_B;
#pragma unroll
        for (int ks = 0; ks < 2; ++ks) {
            const uint32_t kb = (uint32_t)(ks * 32);
            uint32_t bH[4], bL[4];
            {
                const uint32_t bd = sb + SB_HI + (warp_n * 16 + lrow) * ROWB + lhalf * 16 + kb;
                ldsm4(bH, bd);
                ldsm4(bL, bd + (SB_LO - SB_HI));
            }
            uint32_t aH[4][4], aL[4][4];
#pragma unroll
            for (int i = 0; i < 4; ++i) {
                const uint32_t ad = sb + SA_HI + (warp_m * 64 + i * 16 + lrow) * ROWB + lhalf * 16 + kb;
                ldsm4(aH[i], ad);
                ldsm4(aL[i], ad + (SA_LO - SA_HI));
            }
#pragma unroll
            for (int i = 0; i < 4; ++i) {
#pragma unroll
                for (int j = 0; j < 2; ++j) {
                    const uint32_t b0h = (j == 0) ? bH[0] : bH[1];
                    const uint32_t b1h = (j == 0) ? bH[2] : bH[3];
                    const uint32_t b0l = (j == 0) ? bL[0] : bL[1];
                    const uint32_t b1l = (j == 0) ? bL[2] : bL[3];
                    mma16816(acc[i][j], aH[i], b0h, b1h);
                    mma16816(acc[i][j], aH[i], b0l, b1l);
                    mma16816(acc[i][j], aL[i], b0h, b1h);
                }
            }
        }
        __syncthreads();
    }

    const int grp = lane >> 2, t4 = lane & 3;
#pragma unroll
    for (int i = 0; i < 4; ++i) {
#pragma unroll
        for (int j = 0; j < 2; ++j) {
#pragma unroll
            for (int e = 0; e < 4; ++e) {
                const int m = m0 + warp_m * 64 + i * 16 + grp + (e >> 1) * 8;
                const int n = n0 + warp_n * 16 + j * 8 + t4 * 2 + (e & 1);
                float r = acc[i][j][e];
                if (MODE == 0 || MODE == 1) {
                    r += bias[n];
                    const int b = m >> 11, ntok = m & 2047;
                    const int h = n / 96, d = n - h * 96;
                    const int bhh = b * 8 + h;
                    __nv_bfloat16 hi = __float2bfloat16(r);
                    __nv_bfloat16 lo = __float2bfloat16(r - __bfloat162float(hi));
                    if (MODE == 0) {
                        g_qk[((size_t)bhh * N_ + ntok) * D_ + d] = r;
                        const size_t qo = ((size_t)bhh * N_ + ntok) * DPAD + d;
                        g_qhi[qo] = hi; g_qlo[qo] = lo;
                    } else {
                        g_v[((size_t)bhh * N_ + ntok) * D_ + d] = r;
                        const size_t vo = ((size_t)bhh * DPAD + d) * N_ + ntok;
                        g_vthi[vo] = hi; g_vtlo[vo] = lo;
                    }
                } else {
                    outp[(size_t)m * C_ + n] = 0.5f * r + bias[n];
                }
            }
        }
    }
}

// ===========================================================================
// Fused flash attention (branch 1): scores + online softmax + PV.
// Grid (N/128, BH), 256 threads = 8 warps; warp w owns q rows [w*16, w*16+16).
// q hi/lo in registers; K/V tiles (64 kv x 96 d, hi+lo) double-buffered.
// ===========================================================================
#define FA_ROWK 208                         // 96*2 + 16 pad bytes
#define FA_ROWV 144                         // 64*2 + 16 pad bytes
#define FA_SKHI 0
#define FA_SKLO (64 * FA_ROWK)              // 13312
#define FA_SVHI (2 * 64 * FA_ROWK)          // 26624
#define FA_SVLO (FA_SVHI + 96 * FA_ROWV)    // 40448
#define FA_STAGE (FA_SVLO + 96 * FA_ROWV)   // 54272
#define FA_SMEM (2 * FA_STAGE)              // 108544

__global__ __launch_bounds__(256) void fa_kernel()
{
    extern __shared__ __align__(128) char sm[];
    const uint32_t sbase = smem_to_u32(sm);
    const int tid = threadIdx.x, wid = tid >> 5, lane = tid & 31;
    const int bh = blockIdx.y;
    const int q0 = blockIdx.x * 128;
    const int g = lane >> 2, t4 = lane & 3;

    const __nv_bfloat16* qhi  = g_qhi  + (size_t)bh * N_ * DPAD;
    const __nv_bfloat16* qlo  = g_qlo  + (size_t)bh * N_ * DPAD;
    const __nv_bfloat16* vthi = g_vthi + (size_t)bh * DPAD * N_;
    const __nv_bfloat16* vtlo = g_vtlo + (size_t)bh * DPAD * N_;

    // q fragments for this warp's 16 rows: 6 k-steps over d=96
    uint32_t qh[6][4], ql[6][4];
    {
        const int r0 = q0 + wid * 16 + g;
#pragma unroll
        for (int ks = 0; ks < 6; ks++) {
            const int c0 = ks * 16 + 2 * t4;
            qh[ks][0] = *(const uint32_t*)(qhi + (size_t)r0 * DPAD + c0);
            qh[ks][1] = *(const uint32_t*)(qhi + (size_t)(r0 + 8) * DPAD + c0);
            qh[ks][2] = *(const uint32_t*)(qhi + (size_t)r0 * DPAD + c0 + 8);
            qh[ks][3] = *(const uint32_t*)(qhi + (size_t)(r0 + 8) * DPAD + c0 + 8);
            ql[ks][0] = *(const uint32_t*)(qlo + (size_t)r0 * DPAD + c0);
            ql[ks][1] = *(const uint32_t*)(qlo + (size_t)(r0 + 8) * DPAD + c0);
            ql[ks][2] = *(const uint32_t*)(qlo + (size_t)r0 * DPAD + c0 + 8);
            ql[ks][3] = *(const uint32_t*)(qlo + (size_t)(r0 + 8) * DPAD + c0 + 8);
        }
    }

    float O[12][4];
#pragma unroll
    for (int i = 0; i < 12; i++)
#pragma unroll
        for (int e = 0; e < 4; e++) O[i][e] = 0.f;
    float m0v = -1e30f, m1v = -1e30f, l0v = 0.f, l1v = 0.f;

    auto issue = [&](int it) {
        const uint32_t sb = sbase + (uint32_t)(it & 1) * FA_STAGE;
        const int kb = it * 64;
#pragma unroll
        for (int i = 0; i < 12; i++) {
            const int c = i * 256 + tid;          // segment boundaries multiple of 256
            if (c < 768) {
                const int r = c / 12, j = c % 12;
                cp16(sb + FA_SKHI + r * FA_ROWK + j * 16, qhi + (size_t)(kb + r) * DPAD + j * 8);
            } else if (c < 1536) {
                const int cc = c - 768, r = cc / 12, j = cc % 12;
                cp16(sb + FA_SKLO + r * FA_ROWK + j * 16, qlo + (size_t)(kb + r) * DPAD + j * 8);
            } else if (c < 2304) {
                const int cc = c - 1536, d = cc / 8, j = cc % 8;
                cp16(sb + FA_SVHI + d * FA_ROWV + j * 16, vthi + (size_t)d * N_ + kb + j * 8);
            } else {
                const int cc = c - 2304, d = cc / 8, j = cc % 8;
                cp16(sb + FA_SVLO + d * FA_ROWV + j * 16, vtlo + (size_t)d * N_ + kb + j * 8);
            }
        }
        cp_commit();
    };

    issue(0);
    const float cst = (float)(0.10206207261596575 * 1.4426950408889634); // scale*log2e
    const uint32_t lrowi = (uint32_t)(lane & 15), lhalf = (uint32_t)(lane >> 4);

    for (int it = 0; it < N_ / 64; ++it) {
        if (it + 1 < N_ / 64) { issue(it + 1); cp_wait<1>(); }
        else                  { cp_wait<0>(); }
        __syncthreads();
        const uint32_t sb = sbase + (uint32_t)(it & 1) * FA_STAGE;

        // ---- scores: S[16 x 64] per warp, 3-product split ----
        float S[8][4];
#pragma unroll
        for (int i = 0; i < 8; i++)
#pragma unroll
            for (int e = 0; e < 4; e++) S[i][e] = 0.f;

#pragma unroll
        for (int ks = 0; ks < 6; ks++) {
#pragma unroll
            for (int u = 0; u < 4; u++) {
                uint32_t bH[4], bL[4];
                const uint32_t ba = sb + FA_SKHI + (u * 16 + lrowi) * FA_ROWK + ks * 32 + lhalf * 16;
                ldsm4(bH, ba);
                ldsm4(bL, ba + (FA_SKLO - FA_SKHI));
                mma16816(S[2*u],   qh[ks], bH[0], bH[2]);
                mma16816(S[2*u],   qh[ks], bL[0], bL[2]);
                mma16816(S[2*u],   ql[ks], bH[0], bH[2]);
                mma16816(S[2*u+1], qh[ks], bH[1], bH[3]);
                mma16816(S[2*u+1], qh[ks], bL[1], bL[3]);
                mma16816(S[2*u+1], ql[ks], bH[1], bH[3]);
            }
        }

        // ---- online softmax (rows g and g+8) ----
        float c0 = -1e30f, c1 = -1e30f;
#pragma unroll
        for (int i = 0; i < 8; i++) {
            c0 = fmaxf(c0, fmaxf(S[i][0], S[i][1]));
            c1 = fmaxf(c1, fmaxf(S[i][2], S[i][3]));
        }
        c0 = fmaxf(c0, __shfl_xor_sync(0xffffffffu, c0, 1));
        c0 = fmaxf(c0, __shfl_xor_sync(0xffffffffu, c0, 2));
        c1 = fmaxf(c1, __shfl_xor_sync(0xffffffffu, c1, 1));
        c1 = fmaxf(c1, __shfl_xor_sync(0xffffffffu, c1, 2));
        const float m0n = fmaxf(m0v, c0), m1n = fmaxf(m1v, c1);
        const float b0 = m0n * cst, b1 = m1n * cst;
        const float f0 = ex2f(fmaf(m0v, cst, -b0));
        const float f1 = ex2f(fmaf(m1v, cst, -b1));
        m0v = m0n; m1v = m1n;

        float s0 = 0.f, s1 = 0.f;
#pragma unroll
        for (int i = 0; i < 8; i++) {
            S[i][0] = ex2f(fmaf(S[i][0], cst, -b0));
            S[i][1] = ex2f(fmaf(S[i][1], cst, -b0));
            S[i][2] = ex2f(fmaf(S[i][2], cst, -b1));
            S[i][3] = ex2f(fmaf(S[i][3], cst, -b1));
            s0 += S[i][0] + S[i][1];
            s1 += S[i][2] + S[i][3];
        }
        s0 += __shfl_xor_sync(0xffffffffu, s0, 1);
        s0 += __shfl_xor_sync(0xffffffffu, s0, 2);
        s1 += __shfl_xor_sync(0xffffffffu, s1, 1);
        s1 += __shfl_xor_sync(0xffffffffu, s1, 2);
        l0v = l0v * f0 + s0;
        l1v = l1v * f1 + s1;

#pragma unroll
        for (int i = 0; i < 12; i++) {
            O[i][0] *= f0; O[i][1] *= f0; O[i][2] *= f1; O[i][3] *= f1;
        }

        // ---- P fragments (C layout == A layout for m16n8k16) ----
        uint32_t ph[4][4], pl[4][4];
#pragma unroll
        for (int j = 0; j < 4; j++) {
            pack_split(S[2*j][0],   S[2*j][1],   ph[j][0], pl[j][0]);
            pack_split(S[2*j][2],   S[2*j][3],   ph[j][1], pl[j][1]);
            pack_split(S[2*j+1][0], S[2*j+1][1], ph[j][2], pl[j][2]);
            pack_split(S[2*j+1][2], S[2*j+1][3], ph[j][3], pl[j][3]);
        }

        // ---- O += P @ V (3-product) ----
#pragma unroll
        for (int j = 0; j < 4; j++) {
#pragma unroll
            for (int u = 0; u < 6; u++) {
                uint32_t bH[4], bL[4];
                const uint32_t ba = sb + FA_SVHI + (u * 16 + lrowi) * FA_ROWV + j * 32 + lhalf * 16;
                ldsm4(bH, ba);
                ldsm4(bL, ba + (FA_SVLO - FA_SVHI));
                mma16816(O[2*u],   ph[j], bH[0], bH[2]);
                mma16816(O[2*u],   ph[j], bL[0], bL[2]);
                mma16816(O[2*u],   pl[j], bH[0], bH[2]);
                mma16816(O[2*u+1], ph[j], bH[1], bH[3]);
                mma16816(O[2*u+1], ph[j], bL[1], bL[3]);
                mma16816(O[2*u+1], pl[j], bH[1], bH[3]);
            }
        }
        __syncthreads();
    }

    // ---- epilogue: out1 = O / l -> g_s ----
    const int b = bh >> 3, h = bh & 7;
    const float inv0 = 1.f / l0v, inv1 = 1.f / l1v;
    const int r0 = q0 + wid * 16 + g;
    float* d0 = g_s + (size_t)(b * N_ + r0) * C_ + h * 96;
    float* d1 = g_s + (size_t)(b * N_ + r0 + 8) * C_ + h * 96;
#pragma unroll
    for (int i = 0; i < 12; i++) {
        d0[i * 8 + 2 * t4]     = O[i][0] * inv0;
        d0[i * 8 + 2 * t4 + 1] = O[i][1] * inv0;
        d1[i * 8 + 2 * t4]     = O[i][2] * inv1;
        d1[i * 8 + 2 * t4 + 1] = O[i][3] * inv1;
    }
}

// ===========================================================================
// Branch 2: per-token projected channel attention; g_s += x_ca
// ===========================================================================
__global__ __launch_bounds__(128) void branch2_kernel(
    const float* __restrict__ We, const float* __restrict__ be,
    const float* __restrict__ Wf, const float* __restrict__ bf)
{
    __shared__ float sQ[768];
    __shared__ float sV[768];
    __shared__ float sKp[256];
    __shared__ float sVp[256];
    __shared__ float sA[32 * 96];

    const int t = threadIdx.x;
    const size_t tok = blockIdx.x;
    const int b = (int)(tok >> 11), ntok = (int)(tok & 2047);

    for (int i = t; i < 192; i += 128) {
        const int i4 = i * 4;
        const int h = i4 / 96, d = i4 - h * 96;
        const size_t off = ((size_t)(b * 8 + h) * N_ + ntok) * D_ + d;
        ((float4*)sQ)[i] = *(const float4*)(g_qk + off);
        ((float4*)sV)[i] = *(const float4*)(g_v + off);
    }
    __syncthreads();

    for (int p = t; p < 256; p += 128) {
        const int h = p >> 5, e = p & 31;
        float accK = be[e], accV = bf[e];
        const float* wK = We + e * 96;
        const float* wF = Wf + e * 96;
        const float* qh = sQ + h * 96;
        const float* vh = sV + h * 96;
#pragma unroll 8
        for (int d = 0; d < 96; d++) {
            accK = fmaf(qh[d], wK[d], accK);
            accV = fmaf(vh[d], wF[d], accV);
        }
        sKp[e * 8 + h] = accK;
        sVp[h * 32 + e] = accV;
    }
    __syncthreads();

    {
        const int e = t >> 2, qtr = t & 3;
        float a[24];
        float amax = -1e30f;
#pragma unroll
        for (int i = 0; i < 24; i++) {
            const int d = qtr * 24 + i;
            float s = 0.f;
#pragma unroll
            for (int h = 0; h < 8; h++)
                s = fmaf(sKp[e * 8 + h], sQ[h * 96 + d], s);
            a[i] = s;
            amax = fmaxf(amax, s);
        }
        amax = fmaxf(amax, __shfl_xor_sync(0xffffffffu, amax, 1));
        amax = fmaxf(amax, __shfl_xor_sync(0xffffffffu, amax, 2));
        float asum = 0.f;
#pragma unroll
        for (int i = 0; i < 24; i++) { a[i] = __expf(a[i] - amax); asum += a[i]; }
        asum += __shfl_xor_sync(0xffffffffu, asum, 1);
        asum += __shfl_xor_sync(0xffffffffu, asum, 2);
        const float ainv = 1.f / asum;
#pragma unroll
        for (int i = 0; i < 24; i++) sA[e * 96 + qtr * 24 + i] = a[i] * ainv;
    }
    __syncthreads();

    for (int p = t; p < 768; p += 128) {
        const int h = p / 96, d = p - h * 96;
        float s = 0.f;
        const float* vp = sVp + h * 32;
#pragma unroll 8
        for (int e2 = 0; e2 < 32; e2++)
            s = fmaf(vp[e2], sA[e2 * 96 + d], s);
        g_s[tok * C_ + p] += s;
    }
}

// ===========================================================================
// Launch
// ===========================================================================
extern "C" void kernel_launch(void* const* d_in, const int* in_sizes, int n_in,
                              void* d_out, int out_size)
{
    const float* x   = (const float*)d_in[0];
    const float* Wqk = (const float*)d_in[1];
    const float* bqk = (const float*)d_in[2];
    const float* Wv  = (const float*)d_in[3];
    const float* bv  = (const float*)d_in[4];
    const float* Wo  = (const float*)d_in[5];
    const float* bo  = (const float*)d_in[6];
    const float* We  = (const float*)d_in[7];
    const float* be  = (const float*)d_in[8];
    const float* Wf  = (const float*)d_in[9];
    const float* bf  = (const float*)d_in[10];
    float* out = (float*)d_out;

    void *p_xhi, *p_xlo, *p_wqkhi, *p_wqklo, *p_wvhi, *p_wvlo, *p_wohi, *p_wolo;
    void *p_shi, *p_slo, *p_s;
    cudaGetSymbolAddress(&p_xhi, g_xhi);     cudaGetSymbolAddress(&p_xlo, g_xlo);
    cudaGetSymbolAddress(&p_wqkhi, g_Wqkhi); cudaGetSymbolAddress(&p_wqklo, g_Wqklo);
    cudaGetSymbolAddress(&p_wvhi, g_Wvhi);   cudaGetSymbolAddress(&p_wvlo, g_Wvlo);
    cudaGetSymbolAddress(&p_wohi, g_Wohi);   cudaGetSymbolAddress(&p_wolo, g_Wolo);
    cudaGetSymbolAddress(&p_shi, g_shi);     cudaGetSymbolAddress(&p_slo, g_slo);
    cudaGetSymbolAddress(&p_s, g_s);

    cudaFuncSetAttribute(mma_gemm<0>, cudaFuncAttributeMaxDynamicSharedMemorySize, GEMM_SMEM);
    cudaFuncSetAttribute(mma_gemm<1>, cudaFuncAttributeMaxDynamicSharedMemorySize, GEMM_SMEM);
    cudaFuncSetAttribute(mma_gemm<4>, cudaFuncAttributeMaxDynamicSharedMemorySize, GEMM_SMEM);
    cudaFuncSetAttribute(fa_kernel,   cudaFuncAttributeMaxDynamicSharedMemorySize, FA_SMEM);

    // 1) hi/lo splits of x and weights
    {
        const int n = TOK * C_;
        split_kernel<<<(n + 255) / 256, 256>>>(x, (__nv_bfloat16*)p_xhi, (__nv_bfloat16*)p_xlo, n);
        const int nw = C_ * C_;
        split_kernel<<<(nw + 255) / 256, 256>>>(Wqk, (__nv_bfloat16*)p_wqkhi, (__nv_bfloat16*)p_wqklo, nw);
        split_kernel<<<(nw + 255) / 256, 256>>>(Wv,  (__nv_bfloat16*)p_wvhi,  (__nv_bfloat16*)p_wvlo,  nw);
        split_kernel<<<(nw + 255) / 256, 256>>>(Wo,  (__nv_bfloat16*)p_wohi,  (__nv_bfloat16*)p_wolo,  nw);
    }

    // 2) projections (M=8192, N=768, K=768)
    dim3 gProj(TOK / 128, C_ / 64);
    mma_gemm<0><<<gProj, 256, GEMM_SMEM>>>(
        (const __nv_bfloat16*)p_xhi, (const __nv_bfloat16*)p_xlo,
        (const __nv_bfloat16*)p_wqkhi, (const __nv_bfloat16*)p_wqklo,
        bqk, nullptr, C_, C_, C_);
    mma_gemm<1><<<gProj, 256, GEMM_SMEM>>>(
        (const __nv_bfloat16*)p_xhi, (const __nv_bfloat16*)p_xlo,
        (const __nv_bfloat16*)p_wvhi, (const __nv_bfloat16*)p_wvlo,
        bv, nullptr, C_, C_, C_);

    // 3) fused flash attention -> g_s = out1
    dim3 gFA(N_ / 128, BH_);
    fa_kernel<<<gFA, 256, FA_SMEM>>>();

    // 4) branch 2: g_s += x_ca
    branch2_kernel<<<TOK, 128>>>(We, be, Wf, bf);

    // 5) split s, then out = 0.5*(s @ Wo^T) + bo
    {
        const int n = TOK * C_;
        split_kernel<<<(n + 255) / 256, 256>>>((const float*)p_s,
                                               (__nv_bfloat16*)p_shi, (__nv_bfloat16*)p_slo, n);
    }
    mma_gemm<4><<<gProj, 256, GEMM_SMEM>>>(
        (const __nv_bfloat16*)p_shi, (const __nv_bfloat16*)p_slo,
        (const __nv_bfloat16*)p_wohi, (const __nv_bfloat16*)p_wolo,
        bo, out, C_, C_, C_);
}

// round 7
// speedup vs baseline: 2.5374x; 1.1317x over previous
#include <cuda_runtime.h>
#include <cuda_bf16.h>
#include <cuda_fp16.h>
#include <cstdint>

// ===========================================================================
// Problem constants
// ===========================================================================
#define B_   4
#define N_   2048
#define C_   768
#define H_   8
#define D_   96
#define BH_  32            // B*H
#define TOK  8192          // B*N
#define DPAD 128           // head dim padded (stride for q16)

// ===========================================================================
// Device-global scratch (allocation-free rule)
// ===========================================================================
__device__ __align__(256) float g_qk[(size_t)BH_ * N_ * D_];   // fp32 q(=k) [bh][n][d]
__device__ __align__(256) float g_v [(size_t)BH_ * N_ * D_];   // fp32 v     [bh][n][d]
__device__ __align__(256) float g_s [(size_t)TOK * C_];        // out1 + x_ca

__device__ __align__(256) __nv_bfloat16 g_xhi[(size_t)TOK * C_],  g_xlo[(size_t)TOK * C_];
__device__ __align__(256) __nv_bfloat16 g_Wqkhi[C_*C_], g_Wqklo[C_*C_];
__device__ __align__(256) __nv_bfloat16 g_Wvhi [C_*C_], g_Wvlo [C_*C_];
__device__ __align__(256) __half g_Wo16[C_*C_];
__device__ __align__(256) __half g_q16 [(size_t)BH_ * N_ * DPAD];   // fp16 q, [bh][n][128]
__device__ __align__(256) __half g_vt16[(size_t)BH_ * D_ * N_];     // fp16 v^T, [bh][d][n]
__device__ __align__(256) __half g_s16 [(size_t)TOK * C_];

// ===========================================================================
// Asm helpers (base ISA, sm_80+)
// ===========================================================================
__device__ __forceinline__ uint32_t smem_to_u32(const void* p) {
    uint32_t a;
    asm("{ .reg .u64 t; cvta.to.shared.u64 t, %1; cvt.u32.u64 %0, t; }" : "=r"(a) : "l"(p));
    return a;
}
__device__ __forceinline__ void cp16(uint32_t s, const void* g) {
    asm volatile("cp.async.cg.shared.global [%0], [%1], 16;" :: "r"(s), "l"(g));
}
__device__ __forceinline__ void cp_commit() {
    asm volatile("cp.async.commit_group;" ::: "memory");
}
template<int NN> __device__ __forceinline__ void cp_wait() {
    asm volatile("cp.async.wait_group %0;" :: "n"(NN) : "memory");
}
__device__ __forceinline__ void ldsm4(uint32_t (&r)[4], uint32_t addr) {
    asm volatile("ldmatrix.sync.aligned.m8n8.x4.shared.b16 {%0,%1,%2,%3}, [%4];"
                 : "=r"(r[0]), "=r"(r[1]), "=r"(r[2]), "=r"(r[3]) : "r"(addr));
}
__device__ __forceinline__ void mma_bf16(float (&d)[4], const uint32_t (&a)[4],
                                         uint32_t b0, uint32_t b1) {
    asm volatile("mma.sync.aligned.m16n8k16.row.col.f32.bf16.bf16.f32 "
                 "{%0,%1,%2,%3}, {%4,%5,%6,%7}, {%8,%9}, {%0,%1,%2,%3};"
                 : "+f"(d[0]), "+f"(d[1]), "+f"(d[2]), "+f"(d[3])
                 : "r"(a[0]), "r"(a[1]), "r"(a[2]), "r"(a[3]), "r"(b0), "r"(b1));
}
__device__ __forceinline__ void mma_f16(float (&d)[4], const uint32_t (&a)[4],
                                        uint32_t b0, uint32_t b1) {
    asm volatile("mma.sync.aligned.m16n8k16.row.col.f32.f16.f16.f32 "
                 "{%0,%1,%2,%3}, {%4,%5,%6,%7}, {%8,%9}, {%0,%1,%2,%3};"
                 : "+f"(d[0]), "+f"(d[1]), "+f"(d[2]), "+f"(d[3])
                 : "r"(a[0]), "r"(a[1]), "r"(a[2]), "r"(a[3]), "r"(b0), "r"(b1));
}
__device__ __forceinline__ float ex2f(float x) {
    float y; asm("ex2.approx.f32 %0, %1;" : "=f"(y) : "f"(x)); return y;
}
__device__ __forceinline__ void pack_h2(float x, float y, uint32_t& r) {
    __half2 h = __float22half2_rn(make_float2(x, y));
    r = *(uint32_t*)&h;
}

// ===========================================================================
// Elementwise converts
// ===========================================================================
__global__ void split_kernel(const float* __restrict__ src,
                             __nv_bfloat16* __restrict__ hi,
                             __nv_bfloat16* __restrict__ lo, int n)
{
    int i = blockIdx.x * blockDim.x + threadIdx.x;
    if (i < n) {
        float v = src[i];
        __nv_bfloat16 h = __float2bfloat16(v);
        hi[i] = h;
        lo[i] = __float2bfloat16(v - __bfloat162float(h));
    }
}
__global__ void half_kernel(const float* __restrict__ src,
                            __half* __restrict__ dst, int n)
{
    int i = blockIdx.x * blockDim.x + threadIdx.x;
    if (i < n) dst[i] = __float2half(src[i]);
}

// ===========================================================================
// bf16 3-product GEMM for the two projections (proven in R4/R6).
// MODE 0: qk-proj (writes g_qk fp32 + g_q16 fp16), MODE 1: v-proj (g_v + g_vt16)
// ===========================================================================
#define ROWB   80
#define SA_HI  0
#define SA_LO  10240
#define SB_HI  20480
#define SB_LO  25600
#define STAGE_B 30720
#define GEMM_SMEM (2 * STAGE_B)

template<int MODE>
__global__ __launch_bounds__(256, 2) void mma_gemm3(
    const __nv_bfloat16* __restrict__ Ahi, const __nv_bfloat16* __restrict__ Alo,
    const __nv_bfloat16* __restrict__ Bhi, const __nv_bfloat16* __restrict__ Blo,
    const float* __restrict__ bias)
{
    extern __shared__ __align__(128) char sm[];
    const uint32_t sbase = smem_to_u32(sm);
    const int tid  = threadIdx.x;
    const int wid  = tid >> 5, lane = tid & 31;
    const int warp_m = wid >> 2, warp_n = wid & 3;

    const int m0 = blockIdx.x * 128;
    const int n0 = blockIdx.y * 64;

    const int ar  = tid >> 2;
    const int acb = (tid & 3) * 16;
    const int ace = (tid & 3) * 8;

    auto issue = [&](int it) {
        const uint32_t sb = sbase + (uint32_t)(it & 1) * STAGE_B;
        const int k0 = it * 32;
#pragma unroll
        for (int p = 0; p < 2; ++p) {
            const int r = ar + p * 64;
            const size_t go = (size_t)(m0 + r) * C_ + k0 + ace;
            const uint32_t so = sb + (uint32_t)(r * ROWB) + acb;
            cp16(so + SA_HI, Ahi + go);
            cp16(so + SA_LO, Alo + go);
        }
        {
            const size_t go = (size_t)(n0 + ar) * C_ + k0 + ace;
            const uint32_t so = sb + (uint32_t)(ar * ROWB) + acb;
            cp16(so + SB_HI, Bhi + go);
            cp16(so + SB_LO, Blo + go);
        }
        cp_commit();
    };

    float acc[4][2][4];
#pragma unroll
    for (int i = 0; i < 4; i++)
#pragma unroll
        for (int j = 0; j < 2; j++)
#pragma unroll
            for (int e = 0; e < 4; e++) acc[i][j][e] = 0.f;

    const int nIter = C_ >> 5;   // 24
    issue(0);

    const uint32_t lrow = (uint32_t)(lane & 15);
    const uint32_t lhalf = (uint32_t)(lane >> 4);

    for (int it = 0; it < nIter; ++it) {
        if (it + 1 < nIter) { issue(it + 1); cp_wait<1>(); }
        else                { cp_wait<0>(); }
        __syncthreads();
        const uint32_t sb = sbase + (uint32_t)(it & 1) * STAGE_B;
#pragma unroll
        for (int ks = 0; ks < 2; ++ks) {
            const uint32_t kb = (uint32_t)(ks * 32);
            uint32_t bH[4], bL[4];
            {
                const uint32_t bd = sb + SB_HI + (warp_n * 16 + lrow) * ROWB + lhalf * 16 + kb;
                ldsm4(bH, bd);
                ldsm4(bL, bd + (SB_LO - SB_HI));
            }
            uint32_t aH[4][4], aL[4][4];
#pragma unroll
            for (int i = 0; i < 4; ++i) {
                const uint32_t ad = sb + SA_HI + (warp_m * 64 + i * 16 + lrow) * ROWB + lhalf * 16 + kb;
                ldsm4(aH[i], ad);
                ldsm4(aL[i], ad + (SA_LO - SA_HI));
            }
#pragma unroll
            for (int i = 0; i < 4; ++i) {
#pragma unroll
                for (int j = 0; j < 2; ++j) {
                    const uint32_t b0h = (j == 0) ? bH[0] : bH[1];
                    const uint32_t b1h = (j == 0) ? bH[2] : bH[3];
                    const uint32_t b0l = (j == 0) ? bL[0] : bL[1];
                    const uint32_t b1l = (j == 0) ? bL[2] : bL[3];
                    mma_bf16(acc[i][j], aH[i], b0h, b1h);
                    mma_bf16(acc[i][j], aH[i], b0l, b1l);
                    mma_bf16(acc[i][j], aL[i], b0h, b1h);
                }
            }
        }
        __syncthreads();
    }

    const int grp = lane >> 2, t4 = lane & 3;
#pragma unroll
    for (int i = 0; i < 4; ++i) {
#pragma unroll
        for (int j = 0; j < 2; ++j) {
#pragma unroll
            for (int e = 0; e < 4; ++e) {
                const int m = m0 + warp_m * 64 + i * 16 + grp + (e >> 1) * 8;
                const int n = n0 + warp_n * 16 + j * 8 + t4 * 2 + (e & 1);
                float r = acc[i][j][e] + bias[n];
                const int b = m >> 11, ntok = m & 2047;
                const int h = n / 96, d = n - h * 96;
                const int bhh = b * 8 + h;
                if (MODE == 0) {
                    g_qk[((size_t)bhh * N_ + ntok) * D_ + d] = r;
                    g_q16[((size_t)bhh * N_ + ntok) * DPAD + d] = __float2half(r);
                } else {
                    g_v[((size_t)bhh * N_ + ntok) * D_ + d] = r;
                    g_vt16[((size_t)bhh * D_ + d) * N_ + ntok] = __float2half(r);
                }
            }
        }
    }
}

// ===========================================================================
// Fused flash attention, fp16 single-product, 4-stage cp.async ring.
// Grid (N/128, BH), 256 threads = 8 warps; warp w owns q rows [w*16, w*16+16).
// ===========================================================================
#define FA_ROWK 208                         // 96*2 + 16 pad
#define FA_ROWV 144                         // 64*2 + 16 pad
#define FA_SK   0
#define FA_SV   (64 * FA_ROWK)              // 13312
#define FA_STAGE (FA_SV + 96 * FA_ROWV)     // 27136
#define FA_SMEM (4 * FA_STAGE)              // 108544

__global__ __launch_bounds__(256) void fa16_kernel()
{
    extern __shared__ __align__(128) char sm[];
    const uint32_t sbase = smem_to_u32(sm);
    const int tid = threadIdx.x, wid = tid >> 5, lane = tid & 31;
    const int bh = blockIdx.y;
    const int q0 = blockIdx.x * 128;
    const int g = lane >> 2, t4 = lane & 3;

    const __half* q16  = g_q16  + (size_t)bh * N_ * DPAD;
    const __half* vt16 = g_vt16 + (size_t)bh * D_ * N_;

    // q fragments: 6 k-steps of 16 over d=96
    uint32_t qf[6][4];
    {
        const int r0 = q0 + wid * 16 + g;
#pragma unroll
        for (int ks = 0; ks < 6; ks++) {
            const int c0 = ks * 16 + 2 * t4;
            qf[ks][0] = *(const uint32_t*)(q16 + (size_t)r0 * DPAD + c0);
            qf[ks][1] = *(const uint32_t*)(q16 + (size_t)(r0 + 8) * DPAD + c0);
            qf[ks][2] = *(const uint32_t*)(q16 + (size_t)r0 * DPAD + c0 + 8);
            qf[ks][3] = *(const uint32_t*)(q16 + (size_t)(r0 + 8) * DPAD + c0 + 8);
        }
    }

    float O[12][4];
#pragma unroll
    for (int i = 0; i < 12; i++)
#pragma unroll
        for (int e = 0; e < 4; e++) O[i][e] = 0.f;
    float m0v = -1e30f, m1v = -1e30f, l0v = 0.f, l1v = 0.f;

    auto issue = [&](int it) {
        const uint32_t sb = sbase + (uint32_t)(it & 3) * FA_STAGE;
        const int kb = it * 64;
#pragma unroll
        for (int i = 0; i < 6; i++) {
            const int c = i * 256 + tid;
            if (c < 768) {           // K tile: 64 rows x 96 fp16 (12 x 16B)
                const int r = c / 12, j = c % 12;
                cp16(sb + FA_SK + r * FA_ROWK + j * 16, q16 + (size_t)(kb + r) * DPAD + j * 8);
            } else {                 // V^T tile: 96 d-rows x 64 kv (8 x 16B)
                const int cc = c - 768, d = cc / 8, j = cc & 7;
                cp16(sb + FA_SV + d * FA_ROWV + j * 16, vt16 + (size_t)d * N_ + kb + j * 8);
            }
        }
        cp_commit();
    };

    issue(0); issue(1); issue(2);
    const float cst = (float)(0.10206207261596575 * 1.4426950408889634); // scale*log2e
    const uint32_t lrowi = (uint32_t)(lane & 15), lhalf = (uint32_t)(lane >> 4);
    const int nIter = N_ / 64;   // 32

    for (int it = 0; it < nIter; ++it) {
        __syncthreads();                              // ring buffer reuse guard
        if (it + 3 < nIter) issue(it + 3); else cp_commit();
        cp_wait<3>();
        __syncthreads();
        const uint32_t sb = sbase + (uint32_t)(it & 3) * FA_STAGE;

        // ---- scores: S[16 x 64] per warp ----
        float S[8][4];
#pragma unroll
        for (int i = 0; i < 8; i++)
#pragma unroll
            for (int e = 0; e < 4; e++) S[i][e] = 0.f;

#pragma unroll
        for (int ks = 0; ks < 6; ks++) {
#pragma unroll
            for (int u = 0; u < 4; u++) {
                uint32_t bF[4];
                ldsm4(bF, sb + FA_SK + (u * 16 + lrowi) * FA_ROWK + ks * 32 + lhalf * 16);
                mma_f16(S[2*u],   qf[ks], bF[0], bF[2]);
                mma_f16(S[2*u+1], qf[ks], bF[1], bF[3]);
            }
        }

        // ---- online softmax (rows g and g+8) ----
        float c0 = -1e30f, c1 = -1e30f;
#pragma unroll
        for (int i = 0; i < 8; i++) {
            c0 = fmaxf(c0, fmaxf(S[i][0], S[i][1]));
            c1 = fmaxf(c1, fmaxf(S[i][2], S[i][3]));
        }
        c0 = fmaxf(c0, __shfl_xor_sync(0xffffffffu, c0, 1));
        c0 = fmaxf(c0, __shfl_xor_sync(0xffffffffu, c0, 2));
        c1 = fmaxf(c1, __shfl_xor_sync(0xffffffffu, c1, 1));
        c1 = fmaxf(c1, __shfl_xor_sync(0xffffffffu, c1, 2));
        const float m0n = fmaxf(m0v, c0), m1n = fmaxf(m1v, c1);
        const float b0 = m0n * cst, b1 = m1n * cst;
        const float f0 = ex2f(fmaf(m0v, cst, -b0));
        const float f1 = ex2f(fmaf(m1v, cst, -b1));
        m0v = m0n; m1v = m1n;

        float s0 = 0.f, s1 = 0.f;
#pragma unroll
        for (int i = 0; i < 8; i++) {
            S[i][0] = ex2f(fmaf(S[i][0], cst, -b0));
            S[i][1] = ex2f(fmaf(S[i][1], cst, -b0));
            S[i][2] = ex2f(fmaf(S[i][2], cst, -b1));
            S[i][3] = ex2f(fmaf(S[i][3], cst, -b1));
            s0 += S[i][0] + S[i][1];
            s1 += S[i][2] + S[i][3];
        }
        s0 += __shfl_xor_sync(0xffffffffu, s0, 1);
        s0 += __shfl_xor_sync(0xffffffffu, s0, 2);
        s1 += __shfl_xor_sync(0xffffffffu, s1, 1);
        s1 += __shfl_xor_sync(0xffffffffu, s1, 2);
        l0v = l0v * f0 + s0;
        l1v = l1v * f1 + s1;

#pragma unroll
        for (int i = 0; i < 12; i++) {
            O[i][0] *= f0; O[i][1] *= f0; O[i][2] *= f1; O[i][3] *= f1;
        }

        // ---- P fragments (C layout == A layout for m16n8k16) ----
        uint32_t pf[4][4];
#pragma unroll
        for (int j = 0; j < 4; j++) {
            pack_h2(S[2*j][0],   S[2*j][1],   pf[j][0]);
            pack_h2(S[2*j][2],   S[2*j][3],   pf[j][1]);
            pack_h2(S[2*j+1][0], S[2*j+1][1], pf[j][2]);
            pack_h2(S[2*j+1][2], S[2*j+1][3], pf[j][3]);
        }

        // ---- O += P @ V ----
#pragma unroll
        for (int j = 0; j < 4; j++) {
#pragma unroll
            for (int u = 0; u < 6; u++) {
                uint32_t bF[4];
                ldsm4(bF, sb + FA_SV + (u * 16 + lrowi) * FA_ROWV + j * 32 + lhalf * 16);
                mma_f16(O[2*u],   pf[j], bF[0], bF[2]);
                mma_f16(O[2*u+1], pf[j], bF[1], bF[3]);
            }
        }
    }

    // ---- epilogue: out1 = O / l -> g_s ----
    const int b = bh >> 3, h = bh & 7;
    const float inv0 = 1.f / l0v, inv1 = 1.f / l1v;
    const int r0 = q0 + wid * 16 + g;
    float* d0 = g_s + (size_t)(b * N_ + r0) * C_ + h * 96;
    float* d1 = g_s + (size_t)(b * N_ + r0 + 8) * C_ + h * 96;
#pragma unroll
    for (int i = 0; i < 12; i++) {
        d0[i * 8 + 2 * t4]     = O[i][0] * inv0;
        d0[i * 8 + 2 * t4 + 1] = O[i][1] * inv0;
        d1[i * 8 + 2 * t4]     = O[i][2] * inv1;
        d1[i * 8 + 2 * t4 + 1] = O[i][3] * inv1;
    }
}

// ===========================================================================
// fp16 single-product GEMM for the output projection.
// out[m,n] = 0.5 * (s16 @ Wo16^T)[m,n] + bo[n]
// ===========================================================================
#define O_SA 0
#define O_SB 10240
#define O_STAGE 15360
#define OUT_SMEM (2 * O_STAGE)

__global__ __launch_bounds__(256, 2) void mma_gemm_out(
    const __half* __restrict__ A, const __half* __restrict__ Bw,
    const float* __restrict__ bias, float* __restrict__ outp)
{
    extern __shared__ __align__(128) char sm[];
    const uint32_t sbase = smem_to_u32(sm);
    const int tid  = threadIdx.x;
    const int wid  = tid >> 5, lane = tid & 31;
    const int warp_m = wid >> 2, warp_n = wid & 3;

    const int m0 = blockIdx.x * 128;
    const int n0 = blockIdx.y * 64;

    auto issue = [&](int it) {
        const uint32_t sb = sbase + (uint32_t)(it & 1) * O_STAGE;
        const int k0 = it * 32;
#pragma unroll
        for (int p = 0; p < 2; ++p) {
            const int idx = p * 256 + tid;
            const int r = idx >> 2, j = idx & 3;
            cp16(sb + O_SA + r * ROWB + j * 16, A + (size_t)(m0 + r) * C_ + k0 + j * 8);
        }
        {
            const int r = tid >> 2, j = tid & 3;
            cp16(sb + O_SB + r * ROWB + j * 16, Bw + (size_t)(n0 + r) * C_ + k0 + j * 8);
        }
        cp_commit();
    };

    float acc[4][2][4];
#pragma unroll
    for (int i = 0; i < 4; i++)
#pragma unroll
        for (int j = 0; j < 2; j++)
#pragma unroll
            for (int e = 0; e < 4; e++) acc[i][j][e] = 0.f;

    const int nIter = C_ >> 5;   // 24
    issue(0);

    const uint32_t lrow = (uint32_t)(lane & 15);
    const uint32_t lhalf = (uint32_t)(lane >> 4);

    for (int it = 0; it < nIter; ++it) {
        if (it + 1 < nIter) { issue(it + 1); cp_wait<1>(); }
        else                { cp_wait<0>(); }
        __syncthreads();
        const uint32_t sb = sbase + (uint32_t)(it & 1) * O_STAGE;
#pragma unroll
        for (int ks = 0; ks < 2; ++ks) {
            const uint32_t kb = (uint32_t)(ks * 32);
            uint32_t bF[4];
            ldsm4(bF, sb + O_SB + (warp_n * 16 + lrow) * ROWB + lhalf * 16 + kb);
            uint32_t aF[4][4];
#pragma unroll
            for (int i = 0; i < 4; ++i)
                ldsm4(aF[i], sb + O_SA + (warp_m * 64 + i * 16 + lrow) * ROWB + lhalf * 16 + kb);
#pragma unroll
            for (int i = 0; i < 4; ++i) {
                mma_f16(acc[i][0], aF[i], bF[0], bF[2]);
                mma_f16(acc[i][1], aF[i], bF[1], bF[3]);
            }
        }
        __syncthreads();
    }

    const int grp = lane >> 2, t4 = lane & 3;
#pragma unroll
    for (int i = 0; i < 4; ++i) {
#pragma unroll
        for (int j = 0; j < 2; ++j) {
#pragma unroll
            for (int e = 0; e < 4; ++e) {
                const int m = m0 + warp_m * 64 + i * 16 + grp + (e >> 1) * 8;
                const int n = n0 + warp_n * 16 + j * 8 + t4 * 2 + (e & 1);
                outp[(size_t)m * C_ + n] = 0.5f * acc[i][j][e] + bias[n];
            }
        }
    }
}

// ===========================================================================
// Branch 2: per-token projected channel attention; g_s += x_ca (fp32)
// ===========================================================================
__global__ __launch_bounds__(128) void branch2_kernel(
    const float* __restrict__ We, const float* __restrict__ be,
    const float* __restrict__ Wf, const float* __restrict__ bf)
{
    __shared__ float sQ[768];
    __shared__ float sV[768];
    __shared__ float sKp[256];
    __shared__ float sVp[256];
    __shared__ float sA[32 * 96];

    const int t = threadIdx.x;
    const size_t tok = blockIdx.x;
    const int b = (int)(tok >> 11), ntok = (int)(tok & 2047);

    for (int i = t; i < 192; i += 128) {
        const int i4 = i * 4;
        const int h = i4 / 96, d = i4 - h * 96;
        const size_t off = ((size_t)(b * 8 + h) * N_ + ntok) * D_ + d;
        ((float4*)sQ)[i] = *(const float4*)(g_qk + off);
        ((float4*)sV)[i] = *(const float4*)(g_v + off);
    }
    __syncthreads();

    for (int p = t; p < 256; p += 128) {
        const int h = p >> 5, e = p & 31;
        float accK = be[e], accV = bf[e];
        const float* wK = We + e * 96;
        const float* wF = Wf + e * 96;
        const float* qh = sQ + h * 96;
        const float* vh = sV + h * 96;
#pragma unroll 8
        for (int d = 0; d < 96; d++) {
            accK = fmaf(qh[d], wK[d], accK);
            accV = fmaf(vh[d], wF[d], accV);
        }
        sKp[e * 8 + h] = accK;
        sVp[h * 32 + e] = accV;
    }
    __syncthreads();

    {
        const int e = t >> 2, qtr = t & 3;
        float a[24];
        float amax = -1e30f;
#pragma unroll
        for (int i = 0; i < 24; i++) {
            const int d = qtr * 24 + i;
            float s = 0.f;
#pragma unroll
            for (int h = 0; h < 8; h++)
                s = fmaf(sKp[e * 8 + h], sQ[h * 96 + d], s);
            a[i] = s;
            amax = fmaxf(amax, s);
        }
        amax = fmaxf(amax, __shfl_xor_sync(0xffffffffu, amax, 1));
        amax = fmaxf(amax, __shfl_xor_sync(0xffffffffu, amax, 2));
        float asum = 0.f;
#pragma unroll
        for (int i = 0; i < 24; i++) { a[i] = __expf(a[i] - amax); asum += a[i]; }
        asum += __shfl_xor_sync(0xffffffffu, asum, 1);
        asum += __shfl_xor_sync(0xffffffffu, asum, 2);
        const float ainv = 1.f / asum;
#pragma unroll
        for (int i = 0; i < 24; i++) sA[e * 96 + qtr * 24 + i] = a[i] * ainv;
    }
    __syncthreads();

    for (int p = t; p < 768; p += 128) {
        const int h = p / 96, d = p - h * 96;
        float s = 0.f;
        const float* vp = sVp + h * 32;
#pragma unroll 8
        for (int e2 = 0; e2 < 32; e2++)
            s = fmaf(vp[e2], sA[e2 * 96 + d], s);
        g_s[tok * C_ + p] += s;
    }
}

// ===========================================================================
// Launch
// ===========================================================================
extern "C" void kernel_launch(void* const* d_in, const int* in_sizes, int n_in,
                              void* d_out, int out_size)
{
    const float* x   = (const float*)d_in[0];
    const float* Wqk = (const float*)d_in[1];
    const float* bqk = (const float*)d_in[2];
    const float* Wv  = (const float*)d_in[3];
    const float* bv  = (const float*)d_in[4];
    const float* Wo  = (const float*)d_in[5];
    const float* bo  = (const float*)d_in[6];
    const float* We  = (const float*)d_in[7];
    const float* be  = (const float*)d_in[8];
    const float* Wf  = (const float*)d_in[9];
    const float* bf  = (const float*)d_in[10];
    float* out = (float*)d_out;

    void *p_xhi, *p_xlo, *p_wqkhi, *p_wqklo, *p_wvhi, *p_wvlo;
    void *p_wo16, *p_s16, *p_s;
    cudaGetSymbolAddress(&p_xhi, g_xhi);     cudaGetSymbolAddress(&p_xlo, g_xlo);
    cudaGetSymbolAddress(&p_wqkhi, g_Wqkhi); cudaGetSymbolAddress(&p_wqklo, g_Wqklo);
    cudaGetSymbolAddress(&p_wvhi, g_Wvhi);   cudaGetSymbolAddress(&p_wvlo, g_Wvlo);
    cudaGetSymbolAddress(&p_wo16, g_Wo16);
    cudaGetSymbolAddress(&p_s16, g_s16);
    cudaGetSymbolAddress(&p_s, g_s);

    cudaFuncSetAttribute(mma_gemm3<0>, cudaFuncAttributeMaxDynamicSharedMemorySize, GEMM_SMEM);
    cudaFuncSetAttribute(mma_gemm3<1>, cudaFuncAttributeMaxDynamicSharedMemorySize, GEMM_SMEM);
    cudaFuncSetAttribute(mma_gemm_out, cudaFuncAttributeMaxDynamicSharedMemorySize, OUT_SMEM);
    cudaFuncSetAttribute(fa16_kernel,  cudaFuncAttributeMaxDynamicSharedMemorySize, FA_SMEM);

    // 1) converts: x, Wqk, Wv -> bf16 hi/lo; Wo -> fp16
    {
        const int n = TOK * C_;
        split_kernel<<<(n + 255) / 256, 256>>>(x, (__nv_bfloat16*)p_xhi, (__nv_bfloat16*)p_xlo, n);
        const int nw = C_ * C_;
        split_kernel<<<(nw + 255) / 256, 256>>>(Wqk, (__nv_bfloat16*)p_wqkhi, (__nv_bfloat16*)p_wqklo, nw);
        split_kernel<<<(nw + 255) / 256, 256>>>(Wv,  (__nv_bfloat16*)p_wvhi,  (__nv_bfloat16*)p_wvlo,  nw);
        half_kernel<<<(nw + 255) / 256, 256>>>(Wo, (__half*)p_wo16, nw);
    }

    // 2) projections (bf16 3-product, M=8192, N=768, K=768)
    dim3 gProj(TOK / 128, C_ / 64);
    mma_gemm3<0><<<gProj, 256, GEMM_SMEM>>>(
        (const __nv_bfloat16*)p_xhi, (const __nv_bfloat16*)p_xlo,
        (const __nv_bfloat16*)p_wqkhi, (const __nv_bfloat16*)p_wqklo, bqk);
    mma_gemm3<1><<<gProj, 256, GEMM_SMEM>>>(
        (const __nv_bfloat16*)p_xhi, (const __nv_bfloat16*)p_xlo,
        (const __nv_bfloat16*)p_wvhi, (const __nv_bfloat16*)p_wvlo, bv);

    // 3) fused flash attention (fp16 single-product) -> g_s = out1
    dim3 gFA(N_ / 128, BH_);
    fa16_kernel<<<gFA, 256, FA_SMEM>>>();

    // 4) branch 2 (fp32): g_s += x_ca
    branch2_kernel<<<TOK, 128>>>(We, be, Wf, bf);

    // 5) s -> fp16, then out = 0.5*(s @ Wo^T) + bo (fp16 single-product)
    {
        const int n = TOK * C_;
        half_kernel<<<(n + 255) / 256, 256>>>((const float*)p_s, (__half*)p_s16, n);
    }
    mma_gemm_out<<<gProj, 256, OUT_SMEM>>>(
        (const __half*)p_s16, (const __half*)p_wo16, bo, out);
}

// round 11
// speedup vs baseline: 2.7111x; 1.0685x over previous
#include <cuda_runtime.h>
#include <cuda_bf16.h>
#include <cuda_fp16.h>
#include <cstdint>

// ===========================================================================
// Problem constants
// ===========================================================================
#define B_   4
#define N_   2048
#define C_   768
#define H_   8
#define D_   96
#define BH_  32            // B*H
#define TOK  8192          // B*N
#define DPAD 128           // head dim padded (stride for q16)

// ===========================================================================
// Device-global scratch (allocation-free rule)
// ===========================================================================
__device__ __align__(256) float g_qk[(size_t)BH_ * N_ * D_];   // fp32 q(=k) [bh][n][d]
__device__ __align__(256) float g_v [(size_t)BH_ * N_ * D_];   // fp32 v     [bh][n][d]
__device__ __align__(256) float g_s [(size_t)TOK * C_];        // out1 (fp32)

__device__ __align__(256) __nv_bfloat16 g_xhi[(size_t)TOK * C_],  g_xlo[(size_t)TOK * C_];
__device__ __align__(256) __nv_bfloat16 g_Wqkhi[C_*C_], g_Wqklo[C_*C_];
__device__ __align__(256) __nv_bfloat16 g_Wvhi [C_*C_], g_Wvlo [C_*C_];
__device__ __align__(256) __half g_Wo16[C_*C_];
__device__ __align__(256) __half g_q16 [(size_t)BH_ * N_ * DPAD];   // fp16 q, [bh][n][128]
__device__ __align__(256) __half g_vt16[(size_t)BH_ * D_ * N_];     // fp16 v^T, [bh][d][n]
__device__ __align__(256) __half g_s16 [(size_t)TOK * C_];          // out1 + x_ca, fp16

// ===========================================================================
// Asm helpers (base ISA, sm_80+)
// ===========================================================================
__device__ __forceinline__ uint32_t smem_to_u32(const void* p) {
    uint32_t a;
    asm("{ .reg .u64 t; cvta.to.shared.u64 t, %1; cvt.u32.u64 %0, t; }" : "=r"(a) : "l"(p));
    return a;
}
__device__ __forceinline__ void cp16(uint32_t s, const void* g) {
    asm volatile("cp.async.cg.shared.global [%0], [%1], 16;" :: "r"(s), "l"(g));
}
__device__ __forceinline__ void cp_commit() {
    asm volatile("cp.async.commit_group;" ::: "memory");
}
template<int NN> __device__ __forceinline__ void cp_wait() {
    asm volatile("cp.async.wait_group %0;" :: "n"(NN) : "memory");
}
__device__ __forceinline__ void ldsm4(uint32_t (&r)[4], uint32_t addr) {
    asm volatile("ldmatrix.sync.aligned.m8n8.x4.shared.b16 {%0,%1,%2,%3}, [%4];"
                 : "=r"(r[0]), "=r"(r[1]), "=r"(r[2]), "=r"(r[3]) : "r"(addr));
}
__device__ __forceinline__ void mma_bf16(float (&d)[4], const uint32_t (&a)[4],
                                         uint32_t b0, uint32_t b1) {
    asm volatile("mma.sync.aligned.m16n8k16.row.col.f32.bf16.bf16.f32 "
                 "{%0,%1,%2,%3}, {%4,%5,%6,%7}, {%8,%9}, {%0,%1,%2,%3};"
                 : "+f"(d[0]), "+f"(d[1]), "+f"(d[2]), "+f"(d[3])
                 : "r"(a[0]), "r"(a[1]), "r"(a[2]), "r"(a[3]), "r"(b0), "r"(b1));
}
__device__ __forceinline__ void mma_f16(float (&d)[4], const uint32_t (&a)[4],
                                        uint32_t b0, uint32_t b1) {
    asm volatile("mma.sync.aligned.m16n8k16.row.col.f32.f16.f16.f32 "
                 "{%0,%1,%2,%3}, {%4,%5,%6,%7}, {%8,%9}, {%0,%1,%2,%3};"
                 : "+f"(d[0]), "+f"(d[1]), "+f"(d[2]), "+f"(d[3])
                 : "r"(a[0]), "r"(a[1]), "r"(a[2]), "r"(a[3]), "r"(b0), "r"(b1));
}
__device__ __forceinline__ float ex2f(float x) {
    float y; asm("ex2.approx.f32 %0, %1;" : "=f"(y) : "f"(x)); return y;
}
__device__ __forceinline__ void pack_h2(float x, float y, uint32_t& r) {
    __half2 h = __float22half2_rn(make_float2(x, y));
    r = *(uint32_t*)&h;
}

// ===========================================================================
// Elementwise converts
// ===========================================================================
__global__ void split_kernel(const float* __restrict__ src,
                             __nv_bfloat16* __restrict__ hi,
                             __nv_bfloat16* __restrict__ lo, int n)
{
    int i = blockIdx.x * blockDim.x + threadIdx.x;
    if (i < n) {
        float v = src[i];
        __nv_bfloat16 h = __float2bfloat16(v);
        hi[i] = h;
        lo[i] = __float2bfloat16(v - __bfloat162float(h));
    }
}
__global__ void half_kernel(const float* __restrict__ src,
                            __half* __restrict__ dst, int n)
{
    int i = blockIdx.x * blockDim.x + threadIdx.x;
    if (i < n) dst[i] = __float2half(src[i]);
}

// ===========================================================================
// bf16 3-product GEMM for the two projections (proven R4-R7).
// MODE 0: qk-proj (g_qk fp32 + g_q16), MODE 1: v-proj (g_v + g_vt16)
// ===========================================================================
#define ROWB   80
#define SA_HI  0
#define SA_LO  10240
#define SB_HI  20480
#define SB_LO  25600
#define STAGE_B 30720
#define GEMM_SMEM (2 * STAGE_B)

template<int MODE>
__global__ __launch_bounds__(256, 2) void mma_gemm3(
    const __nv_bfloat16* __restrict__ Ahi, const __nv_bfloat16* __restrict__ Alo,
    const __nv_bfloat16* __restrict__ Bhi, const __nv_bfloat16* __restrict__ Blo,
    const float* __restrict__ bias)
{
    extern __shared__ __align__(128) char sm[];
    const uint32_t sbase = smem_to_u32(sm);
    const int tid  = threadIdx.x;
    const int wid  = tid >> 5, lane = tid & 31;
    const int warp_m = wid >> 2, warp_n = wid & 3;

    const int m0 = blockIdx.x * 128;
    const int n0 = blockIdx.y * 64;

    const int ar  = tid >> 2;
    const int acb = (tid & 3) * 16;
    const int ace = (tid & 3) * 8;

    auto issue = [&](int it) {
        const uint32_t sb = sbase + (uint32_t)(it & 1) * STAGE_B;
        const int k0 = it * 32;
#pragma unroll
        for (int p = 0; p < 2; ++p) {
            const int r = ar + p * 64;
            const size_t go = (size_t)(m0 + r) * C_ + k0 + ace;
            const uint32_t so = sb + (uint32_t)(r * ROWB) + acb;
            cp16(so + SA_HI, Ahi + go);
            cp16(so + SA_LO, Alo + go);
        }
        {
            const size_t go = (size_t)(n0 + ar) * C_ + k0 + ace;
            const uint32_t so = sb + (uint32_t)(ar * ROWB) + acb;
            cp16(so + SB_HI, Bhi + go);
            cp16(so + SB_LO, Blo + go);
        }
        cp_commit();
    };

    float acc[4][2][4];
#pragma unroll
    for (int i = 0; i < 4; i++)
#pragma unroll
        for (int j = 0; j < 2; j++)
#pragma unroll
            for (int e = 0; e < 4; e++) acc[i][j][e] = 0.f;

    const int nIter = C_ >> 5;   // 24
    issue(0);

    const uint32_t lrow = (uint32_t)(lane & 15);
    const uint32_t lhalf = (uint32_t)(lane >> 4);

    for (int it = 0; it < nIter; ++it) {
        if (it + 1 < nIter) { issue(it + 1); cp_wait<1>(); }
        else                { cp_wait<0>(); }
        __syncthreads();
        const uint32_t sb = sbase + (uint32_t)(it & 1) * STAGE_B;
#pragma unroll
        for (int ks = 0; ks < 2; ++ks) {
            const uint32_t kb = (uint32_t)(ks * 32);
            uint32_t bH[4], bL[4];
            {
                const uint32_t bd = sb + SB_HI + (warp_n * 16 + lrow) * ROWB + lhalf * 16 + kb;
                ldsm4(bH, bd);
                ldsm4(bL, bd + (SB_LO - SB_HI));
            }
            uint32_t aH[4][4], aL[4][4];
#pragma unroll
            for (int i = 0; i < 4; ++i) {
                const uint32_t ad = sb + SA_HI + (warp_m * 64 + i * 16 + lrow) * ROWB + lhalf * 16 + kb;
                ldsm4(aH[i], ad);
                ldsm4(aL[i], ad + (SA_LO - SA_HI));
            }
#pragma unroll
            for (int i = 0; i < 4; ++i) {
#pragma unroll
                for (int j = 0; j < 2; ++j) {
                    const uint32_t b0h = (j == 0) ? bH[0] : bH[1];
                    const uint32_t b1h = (j == 0) ? bH[2] : bH[3];
                    const uint32_t b0l = (j == 0) ? bL[0] : bL[1];
                    const uint32_t b1l = (j == 0) ? bL[2] : bL[3];
                    mma_bf16(acc[i][j], aH[i], b0h, b1h);
                    mma_bf16(acc[i][j], aH[i], b0l, b1l);
                    mma_bf16(acc[i][j], aL[i], b0h, b1h);
                }
            }
        }
        __syncthreads();
    }

    const int grp = lane >> 2, t4 = lane & 3;
#pragma unroll
    for (int i = 0; i < 4; ++i) {
#pragma unroll
        for (int j = 0; j < 2; ++j) {
#pragma unroll
            for (int e = 0; e < 4; ++e) {
                const int m = m0 + warp_m * 64 + i * 16 + grp + (e >> 1) * 8;
                const int n = n0 + warp_n * 16 + j * 8 + t4 * 2 + (e & 1);
                float r = acc[i][j][e] + bias[n];
                const int b = m >> 11, ntok = m & 2047;
                const int h = n / 96, d = n - h * 96;
                const int bhh = b * 8 + h;
                if (MODE == 0) {
                    g_qk[((size_t)bhh * N_ + ntok) * D_ + d] = r;
                    g_q16[((size_t)bhh * N_ + ntok) * DPAD + d] = __float2half(r);
                } else {
                    g_v[((size_t)bhh * N_ + ntok) * D_ + d] = r;
                    g_vt16[((size_t)bhh * D_ + d) * N_ + ntok] = __float2half(r);
                }
            }
        }
    }
}

// ===========================================================================
// Fused flash attention, fp16, kv-tile 128 (16 iterations), 2-stage ring.
// Grid (N/128, BH), 256 threads = 8 warps; warp w owns q rows [w*16, w*16+16).
// ===========================================================================
#define FA_ROWK 208                         // 96*2 + 16 pad
#define FA_ROWV 272                         // 128*2 + 16 pad
#define FA_SK   0
#define FA_SV   (128 * FA_ROWK)             // 26624
#define FA_STAGE (FA_SV + 96 * FA_ROWV)     // 52736
#define FA_SMEM (2 * FA_STAGE)              // 105472

__global__ __launch_bounds__(256) void fa16_kernel()
{
    extern __shared__ __align__(128) char sm[];
    const uint32_t sbase = smem_to_u32(sm);
    const int tid = threadIdx.x, wid = tid >> 5, lane = tid & 31;
    const int bh = blockIdx.y;
    const int q0 = blockIdx.x * 128;
    const int g = lane >> 2, t4 = lane & 3;

    const __half* q16  = g_q16  + (size_t)bh * N_ * DPAD;
    const __half* vt16 = g_vt16 + (size_t)bh * D_ * N_;

    // q fragments: 6 k-steps of 16 over d=96
    uint32_t qf[6][4];
    {
        const int r0 = q0 + wid * 16 + g;
#pragma unroll
        for (int ks = 0; ks < 6; ks++) {
            const int c0 = ks * 16 + 2 * t4;
            qf[ks][0] = *(const uint32_t*)(q16 + (size_t)r0 * DPAD + c0);
            qf[ks][1] = *(const uint32_t*)(q16 + (size_t)(r0 + 8) * DPAD + c0);
            qf[ks][2] = *(const uint32_t*)(q16 + (size_t)r0 * DPAD + c0 + 8);
            qf[ks][3] = *(const uint32_t*)(q16 + (size_t)(r0 + 8) * DPAD + c0 + 8);
        }
    }

    float O[12][4];
#pragma unroll
    for (int i = 0; i < 12; i++)
#pragma unroll
        for (int e = 0; e < 4; e++) O[i][e] = 0.f;
    float m0v = -1e30f, m1v = -1e30f, l0v = 0.f, l1v = 0.f;

    auto issue = [&](int it) {
        const uint32_t sb = sbase + (uint32_t)(it & 1) * FA_STAGE;
        const int kb = it * 128;
#pragma unroll
        for (int i = 0; i < 12; i++) {
            const int c = i * 256 + tid;
            if (c < 1536) {          // K tile: 128 rows x 96 fp16 (12 x 16B)
                const int r = c / 12, j = c % 12;
                cp16(sb + FA_SK + r * FA_ROWK + j * 16, q16 + (size_t)(kb + r) * DPAD + j * 8);
            } else {                 // V^T tile: 96 d-rows x 128 kv (16 x 16B)
                const int cc = c - 1536, d = cc >> 4, j = cc & 15;
                cp16(sb + FA_SV + d * FA_ROWV + j * 16, vt16 + (size_t)d * N_ + kb + j * 8);
            }
        }
        cp_commit();
    };

    issue(0);
    const float cst = (float)(0.10206207261596575 * 1.4426950408889634); // scale*log2e
    const uint32_t lrowi = (uint32_t)(lane & 15), lhalf = (uint32_t)(lane >> 4);
    const int nIter = N_ / 128;   // 16

    for (int it = 0; it < nIter; ++it) {
        if (it + 1 < nIter) { issue(it + 1); cp_wait<1>(); }
        else                { cp_wait<0>(); }
        __syncthreads();
        const uint32_t sb = sbase + (uint32_t)(it & 1) * FA_STAGE;

        // ---- scores: S[16 x 128] per warp ----
        float S[16][4];
#pragma unroll
        for (int i = 0; i < 16; i++)
#pragma unroll
            for (int e = 0; e < 4; e++) S[i][e] = 0.f;

#pragma unroll
        for (int ks = 0; ks < 6; ks++) {
#pragma unroll
            for (int u = 0; u < 8; u++) {
                uint32_t bF[4];
                ldsm4(bF, sb + FA_SK + (u * 16 + lrowi) * FA_ROWK + ks * 32 + lhalf * 16);
                mma_f16(S[2*u],   qf[ks], bF[0], bF[2]);
                mma_f16(S[2*u+1], qf[ks], bF[1], bF[3]);
            }
        }

        // ---- online softmax (rows g and g+8) ----
        float c0 = -1e30f, c1 = -1e30f;
#pragma unroll
        for (int i = 0; i < 16; i++) {
            c0 = fmaxf(c0, fmaxf(S[i][0], S[i][1]));
            c1 = fmaxf(c1, fmaxf(S[i][2], S[i][3]));
        }
        c0 = fmaxf(c0, __shfl_xor_sync(0xffffffffu, c0, 1));
        c0 = fmaxf(c0, __shfl_xor_sync(0xffffffffu, c0, 2));
        c1 = fmaxf(c1, __shfl_xor_sync(0xffffffffu, c1, 1));
        c1 = fmaxf(c1, __shfl_xor_sync(0xffffffffu, c1, 2));
        const float m0n = fmaxf(m0v, c0), m1n = fmaxf(m1v, c1);
        const float b0 = m0n * cst, b1 = m1n * cst;
        const float f0 = ex2f(fmaf(m0v, cst, -b0));
        const float f1 = ex2f(fmaf(m1v, cst, -b1));
        m0v = m0n; m1v = m1n;

        float s0 = 0.f, s1 = 0.f;
#pragma unroll
        for (int i = 0; i < 16; i++) {
            S[i][0] = ex2f(fmaf(S[i][0], cst, -b0));
            S[i][1] = ex2f(fmaf(S[i][1], cst, -b0));
            S[i][2] = ex2f(fmaf(S[i][2], cst, -b1));
            S[i][3] = ex2f(fmaf(S[i][3], cst, -b1));
            s0 += S[i][0] + S[i][1];
            s1 += S[i][2] + S[i][3];
        }
        s0 += __shfl_xor_sync(0xffffffffu, s0, 1);
        s0 += __shfl_xor_sync(0xffffffffu, s0, 2);
        s1 += __shfl_xor_sync(0xffffffffu, s1, 1);
        s1 += __shfl_xor_sync(0xffffffffu, s1, 2);
        l0v = l0v * f0 + s0;
        l1v = l1v * f1 + s1;

#pragma unroll
        for (int i = 0; i < 12; i++) {
            O[i][0] *= f0; O[i][1] *= f0; O[i][2] *= f1; O[i][3] *= f1;
        }

        // ---- P fragments (C layout == A layout for m16n8k16) ----
        uint32_t pf[8][4];
#pragma unroll
        for (int j = 0; j < 8; j++) {
            pack_h2(S[2*j][0],   S[2*j][1],   pf[j][0]);
            pack_h2(S[2*j][2],   S[2*j][3],   pf[j][1]);
            pack_h2(S[2*j+1][0], S[2*j+1][1], pf[j][2]);
            pack_h2(S[2*j+1][2], S[2*j+1][3], pf[j][3]);
        }

        // ---- O += P @ V ----
#pragma unroll
        for (int j = 0; j < 8; j++) {
#pragma unroll
            for (int u = 0; u < 6; u++) {
                uint32_t bF[4];
                ldsm4(bF, sb + FA_SV + (u * 16 + lrowi) * FA_ROWV + j * 32 + lhalf * 16);
                mma_f16(O[2*u],   pf[j], bF[0], bF[2]);
                mma_f16(O[2*u+1], pf[j], bF[1], bF[3]);
            }
        }
        __syncthreads();
    }

    // ---- epilogue: out1 = O / l -> g_s ----
    const int b = bh >> 3, h = bh & 7;
    const float inv0 = 1.f / l0v, inv1 = 1.f / l1v;
    const int r0 = q0 + wid * 16 + g;
    float* d0 = g_s + (size_t)(b * N_ + r0) * C_ + h * 96;
    float* d1 = g_s + (size_t)(b * N_ + r0 + 8) * C_ + h * 96;
#pragma unroll
    for (int i = 0; i < 12; i++) {
        d0[i * 8 + 2 * t4]     = O[i][0] * inv0;
        d0[i * 8 + 2 * t4 + 1] = O[i][1] * inv0;
        d1[i * 8 + 2 * t4]     = O[i][2] * inv1;
        d1[i * 8 + 2 * t4 + 1] = O[i][3] * inv1;
    }
}

// ===========================================================================
// fp16 single-product GEMM for the output projection.
// out[m,n] = 0.5 * (s16 @ Wo16^T)[m,n] + bo[n]
// ===========================================================================
#define O_SA 0
#define O_SB 10240
#define O_STAGE 15360
#define OUT_SMEM (2 * O_STAGE)

__global__ __launch_bounds__(256, 2) void mma_gemm_out(
    const __half* __restrict__ A, const __half* __restrict__ Bw,
    const float* __restrict__ bias, float* __restrict__ outp)
{
    extern __shared__ __align__(128) char sm[];
    const uint32_t sbase = smem_to_u32(sm);
    const int tid  = threadIdx.x;
    const int wid  = tid >> 5, lane = tid & 31;
    const int warp_m = wid >> 2, warp_n = wid & 3;

    const int m0 = blockIdx.x * 128;
    const int n0 = blockIdx.y * 64;

    auto issue = [&](int it) {
        const uint32_t sb = sbase + (uint32_t)(it & 1) * O_STAGE;
        const int k0 = it * 32;
#pragma unroll
        for (int p = 0; p < 2; ++p) {
            const int idx = p * 256 + tid;
            const int r = idx >> 2, j = idx & 3;
            cp16(sb + O_SA + r * ROWB + j * 16, A + (size_t)(m0 + r) * C_ + k0 + j * 8);
        }
        {
            const int r = tid >> 2, j = tid & 3;
            cp16(sb + O_SB + r * ROWB + j * 16, Bw + (size_t)(n0 + r) * C_ + k0 + j * 8);
        }
        cp_commit();
    };

    float acc[4][2][4];
#pragma unroll
    for (int i = 0; i < 4; i++)
#pragma unroll
        for (int j = 0; j < 2; j++)
#pragma unroll
            for (int e = 0; e < 4; e++) acc[i][j][e] = 0.f;

    const int nIter = C_ >> 5;   // 24
    issue(0);

    const uint32_t lrow = (uint32_t)(lane & 15);
    const uint32_t lhalf = (uint32_t)(lane >> 4);

    for (int it = 0; it < nIter; ++it) {
        if (it + 1 < nIter) { issue(it + 1); cp_wait<1>(); }
        else                { cp_wait<0>(); }
        __syncthreads();
        const uint32_t sb = sbase + (uint32_t)(it & 1) * O_STAGE;
#pragma unroll
        for (int ks = 0; ks < 2; ++ks) {
            const uint32_t kb = (uint32_t)(ks * 32);
            uint32_t bF[4];
            ldsm4(bF, sb + O_SB + (warp_n * 16 + lrow) * ROWB + lhalf * 16 + kb);
            uint32_t aF[4][4];
#pragma unroll
            for (int i = 0; i < 4; ++i)
                ldsm4(aF[i], sb + O_SA + (warp_m * 64 + i * 16 + lrow) * ROWB + lhalf * 16 + kb);
#pragma unroll
            for (int i = 0; i < 4; ++i) {
                mma_f16(acc[i][0], aF[i], bF[0], bF[2]);
                mma_f16(acc[i][1], aF[i], bF[1], bF[3]);
            }
        }
        __syncthreads();
    }

    const int grp = lane >> 2, t4 = lane & 3;
#pragma unroll
    for (int i = 0; i < 4; ++i) {
#pragma unroll
        for (int j = 0; j < 2; ++j) {
#pragma unroll
            for (int e = 0; e < 4; ++e) {
                const int m = m0 + warp_m * 64 + i * 16 + grp + (e >> 1) * 8;
                const int n = n0 + warp_n * 16 + j * 8 + t4 * 2 + (e & 1);
                outp[(size_t)m * C_ + n] = 0.5f * acc[i][j][e] + bias[n];
            }
        }
    }
}

// ===========================================================================
// Branch 2: per-token projected channel attention.
// Reads g_s (out1), adds x_ca, writes g_s16 = fp16(out1 + x_ca).
// ===========================================================================
__global__ __launch_bounds__(128) void branch2_kernel(
    const float* __restrict__ We, const float* __restrict__ be,
    const float* __restrict__ Wf, const float* __restrict__ bf)
{
    __shared__ float sQ[768];
    __shared__ float sV[768];
    __shared__ float sKp[256];
    __shared__ float sVp[256];
    __shared__ float sA[32 * 96];

    const int t = threadIdx.x;
    const size_t tok = blockIdx.x;
    const int b = (int)(tok >> 11), ntok = (int)(tok & 2047);

    for (int i = t; i < 192; i += 128) {
        const int i4 = i * 4;
        const int h = i4 / 96, d = i4 - h * 96;
        const size_t off = ((size_t)(b * 8 + h) * N_ + ntok) * D_ + d;
        ((float4*)sQ)[i] = *(const float4*)(g_qk + off);
        ((float4*)sV)[i] = *(const float4*)(g_v + off);
    }
    __syncthreads();

    for (int p = t; p < 256; p += 128) {
        const int h = p >> 5, e = p & 31;
        float accK = be[e], accV = bf[e];
        const float* wK = We + e * 96;
        const float* wF = Wf + e * 96;
        const float* qh = sQ + h * 96;
        const float* vh = sV + h * 96;
#pragma unroll 8
        for (int d = 0; d < 96; d++) {
            accK = fmaf(qh[d], wK[d], accK);
            accV = fmaf(vh[d], wF[d], accV);
        }
        sKp[e * 8 + h] = accK;
        sVp[h * 32 + e] = accV;
    }
    __syncthreads();

    {
        const int e = t >> 2, qtr = t & 3;
        float a[24];
        float amax = -1e30f;
#pragma unroll
        for (int i = 0; i < 24; i++) {
            const int d = qtr * 24 + i;
            float s = 0.f;
#pragma unroll
            for (int h = 0; h < 8; h++)
                s = fmaf(sKp[e * 8 + h], sQ[h * 96 + d], s);
            a[i] = s;
            amax = fmaxf(amax, s);
        }
        amax = fmaxf(amax, __shfl_xor_sync(0xffffffffu, amax, 1));
        amax = fmaxf(amax, __shfl_xor_sync(0xffffffffu, amax, 2));
        float asum = 0.f;
#pragma unroll
        for (int i = 0; i < 24; i++) { a[i] = __expf(a[i] - amax); asum += a[i]; }
        asum += __shfl_xor_sync(0xffffffffu, asum, 1);
        asum += __shfl_xor_sync(0xffffffffu, asum, 2);
        const float ainv = 1.f / asum;
#pragma unroll
        for (int i = 0; i < 24; i++) sA[e * 96 + qtr * 24 + i] = a[i] * ainv;
    }
    __syncthreads();

    for (int p = t; p < 768; p += 128) {
        const int h = p / 96, d = p - h * 96;
        float s = 0.f;
        const float* vp = sVp + h * 32;
#pragma unroll 8
        for (int e2 = 0; e2 < 32; e2++)
            s = fmaf(vp[e2], sA[e2 * 96 + d], s);
        g_s16[tok * C_ + p] = __float2half(g_s[tok * C_ + p] + s);
    }
}

// ===========================================================================
// Launch
// ===========================================================================
extern "C" void kernel_launch(void* const* d_in, const int* in_sizes, int n_in,
                              void* d_out, int out_size)
{
    const float* x   = (const float*)d_in[0];
    const float* Wqk = (const float*)d_in[1];
    const float* bqk = (const float*)d_in[2];
    const float* Wv  = (const float*)d_in[3];
    const float* bv  = (const float*)d_in[4];
    const float* Wo  = (const float*)d_in[5];
    const float* bo  = (const float*)d_in[6];
    const float* We  = (const float*)d_in[7];
    const float* be  = (const float*)d_in[8];
    const float* Wf  = (const float*)d_in[9];
    const float* bf  = (const float*)d_in[10];
    float* out = (float*)d_out;

    void *p_xhi, *p_xlo, *p_wqkhi, *p_wqklo, *p_wvhi, *p_wvlo;
    void *p_wo16, *p_s16;
    cudaGetSymbolAddress(&p_xhi, g_xhi);     cudaGetSymbolAddress(&p_xlo, g_xlo);
    cudaGetSymbolAddress(&p_wqkhi, g_Wqkhi); cudaGetSymbolAddress(&p_wqklo, g_Wqklo);
    cudaGetSymbolAddress(&p_wvhi, g_Wvhi);   cudaGetSymbolAddress(&p_wvlo, g_Wvlo);
    cudaGetSymbolAddress(&p_wo16, g_Wo16);
    cudaGetSymbolAddress(&p_s16, g_s16);

    cudaFuncSetAttribute(mma_gemm3<0>, cudaFuncAttributeMaxDynamicSharedMemorySize, GEMM_SMEM);
    cudaFuncSetAttribute(mma_gemm3<1>, cudaFuncAttributeMaxDynamicSharedMemorySize, GEMM_SMEM);
    cudaFuncSetAttribute(mma_gemm_out, cudaFuncAttributeMaxDynamicSharedMemorySize, OUT_SMEM);
    cudaFuncSetAttribute(fa16_kernel,  cudaFuncAttributeMaxDynamicSharedMemorySize, FA_SMEM);

    // 1) converts: x, Wqk, Wv -> bf16 hi/lo; Wo -> fp16
    {
        const int n = TOK * C_;
        split_kernel<<<(n + 255) / 256, 256>>>(x, (__nv_bfloat16*)p_xhi, (__nv_bfloat16*)p_xlo, n);
        const int nw = C_ * C_;
        split_kernel<<<(nw + 255) / 256, 256>>>(Wqk, (__nv_bfloat16*)p_wqkhi, (__nv_bfloat16*)p_wqklo, nw);
        split_kernel<<<(nw + 255) / 256, 256>>>(Wv,  (__nv_bfloat16*)p_wvhi,  (__nv_bfloat16*)p_wvlo,  nw);
        half_kernel<<<(nw + 255) / 256, 256>>>(Wo, (__half*)p_wo16, nw);
    }

    // 2) projections (bf16 3-product, M=8192, N=768, K=768)
    dim3 gProj(TOK / 128, C_ / 64);
    mma_gemm3<0><<<gProj, 256, GEMM_SMEM>>>(
        (const __nv_bfloat16*)p_xhi, (const __nv_bfloat16*)p_xlo,
        (const __nv_bfloat16*)p_wqkhi, (const __nv_bfloat16*)p_wqklo, bqk);
    mma_gemm3<1><<<gProj, 256, GEMM_SMEM>>>(
        (const __nv_bfloat16*)p_xhi, (const __nv_bfloat16*)p_xlo,
        (const __nv_bfloat16*)p_wvhi, (const __nv_bfloat16*)p_wvlo, bv);

    // 3) fused flash attention (fp16, kv-tile 128) -> g_s = out1
    dim3 gFA(N_ / 128, BH_);
    fa16_kernel<<<gFA, 256, FA_SMEM>>>();

    // 4) branch 2: g_s16 = fp16(out1 + x_ca)   [convert fused]
    branch2_kernel<<<TOK, 128>>>(We, be, Wf, bf);

    // 5) out = 0.5*(s16 @ Wo16^T) + bo
    mma_gemm_out<<<gProj, 256, OUT_SMEM>>>(
        (const __half*)p_s16, (const __half*)p_wo16, bo, out);
}

// round 12
// speedup vs baseline: 2.9048x; 1.0714x over previous
#include <cuda_runtime.h>
#include <cuda_bf16.h>
#include <cuda_fp16.h>
#include <cstdint>

// ===========================================================================
// Problem constants
// ===========================================================================
#define B_   4
#define N_   2048
#define C_   768
#define H_   8
#define D_   96
#define BH_  32            // B*H
#define TOK  8192          // B*N
#define DPAD 128           // head dim padded (stride for q16)

// ===========================================================================
// Device-global scratch (allocation-free rule)
// ===========================================================================
__device__ __align__(256) float g_qk[(size_t)BH_ * N_ * D_];   // fp32 q(=k) [bh][n][d]
__device__ __align__(256) float g_v [(size_t)BH_ * N_ * D_];   // fp32 v     [bh][n][d]
__device__ __align__(256) float g_s [(size_t)TOK * C_];        // out1 (fp32)

__device__ __align__(256) __half g_x16 [(size_t)TOK * C_];
__device__ __align__(256) __half g_Wqk16[C_*C_];
__device__ __align__(256) __half g_Wv16 [C_*C_];
__device__ __align__(256) __half g_Wo16 [C_*C_];
__device__ __align__(256) __half g_q16 [(size_t)BH_ * N_ * DPAD];   // fp16 q, [bh][n][128]
__device__ __align__(256) __half g_vt16[(size_t)BH_ * D_ * N_];     // fp16 v^T, [bh][d][n]
__device__ __align__(256) __half g_s16 [(size_t)TOK * C_];          // out1 + x_ca, fp16

// ===========================================================================
// Asm helpers (base ISA, sm_80+)
// ===========================================================================
__device__ __forceinline__ uint32_t smem_to_u32(const void* p) {
    uint32_t a;
    asm("{ .reg .u64 t; cvta.to.shared.u64 t, %1; cvt.u32.u64 %0, t; }" : "=r"(a) : "l"(p));
    return a;
}
__device__ __forceinline__ void cp16(uint32_t s, const void* g) {
    asm volatile("cp.async.cg.shared.global [%0], [%1], 16;" :: "r"(s), "l"(g));
}
__device__ __forceinline__ void cp_commit() {
    asm volatile("cp.async.commit_group;" ::: "memory");
}
template<int NN> __device__ __forceinline__ void cp_wait() {
    asm volatile("cp.async.wait_group %0;" :: "n"(NN) : "memory");
}
__device__ __forceinline__ void ldsm4(uint32_t (&r)[4], uint32_t addr) {
    asm volatile("ldmatrix.sync.aligned.m8n8.x4.shared.b16 {%0,%1,%2,%3}, [%4];"
                 : "=r"(r[0]), "=r"(r[1]), "=r"(r[2]), "=r"(r[3]) : "r"(addr));
}
__device__ __forceinline__ void mma_f16(float (&d)[4], const uint32_t (&a)[4],
                                        uint32_t b0, uint32_t b1) {
    asm volatile("mma.sync.aligned.m16n8k16.row.col.f32.f16.f16.f32 "
                 "{%0,%1,%2,%3}, {%4,%5,%6,%7}, {%8,%9}, {%0,%1,%2,%3};"
                 : "+f"(d[0]), "+f"(d[1]), "+f"(d[2]), "+f"(d[3])
                 : "r"(a[0]), "r"(a[1]), "r"(a[2]), "r"(a[3]), "r"(b0), "r"(b1));
}
__device__ __forceinline__ float ex2f(float x) {
    float y; asm("ex2.approx.f32 %0, %1;" : "=f"(y) : "f"(x)); return y;
}
__device__ __forceinline__ void pack_h2(float x, float y, uint32_t& r) {
    __half2 h = __float22half2_rn(make_float2(x, y));
    r = *(uint32_t*)&h;
}

// ===========================================================================
// Elementwise convert fp32 -> fp16
// ===========================================================================
__global__ void half_kernel(const float* __restrict__ src,
                            __half* __restrict__ dst, int n)
{
    int i = blockIdx.x * blockDim.x + threadIdx.x;
    if (i < n) dst[i] = __float2half(src[i]);
}

// ===========================================================================
// fp16 single-product GEMM: D[128x64 tile] = A @ B^T + bias (K=768).
// 256 threads = 8 warps (2m x 4n), warp tile 64x16, BK=32, double buffer.
// MODE 0: qk-proj (g_qk fp32 + g_q16), MODE 1: v-proj (g_v + g_vt16),
// MODE 4: out = 0.5*acc + bias.
// ===========================================================================
#define ROWB   80
#define G_SA 0
#define G_SB 10240
#define G_STAGE 15360
#define GEMM_SMEM (2 * G_STAGE)

template<int MODE>
__global__ __launch_bounds__(256, 2) void gemm16(
    const __half* __restrict__ A, const __half* __restrict__ Bw,
    const float* __restrict__ bias, float* __restrict__ outp)
{
    extern __shared__ __align__(128) char sm[];
    const uint32_t sbase = smem_to_u32(sm);
    const int tid  = threadIdx.x;
    const int wid  = tid >> 5, lane = tid & 31;
    const int warp_m = wid >> 2, warp_n = wid & 3;

    const int m0 = blockIdx.x * 128;
    const int n0 = blockIdx.y * 64;

    auto issue = [&](int it) {
        const uint32_t sb = sbase + (uint32_t)(it & 1) * G_STAGE;
        const int k0 = it * 32;
#pragma unroll
        for (int p = 0; p < 2; ++p) {
            const int idx = p * 256 + tid;
            const int r = idx >> 2, j = idx & 3;
            cp16(sb + G_SA + r * ROWB + j * 16, A + (size_t)(m0 + r) * C_ + k0 + j * 8);
        }
        {
            const int r = tid >> 2, j = tid & 3;
            cp16(sb + G_SB + r * ROWB + j * 16, Bw + (size_t)(n0 + r) * C_ + k0 + j * 8);
        }
        cp_commit();
    };

    float acc[4][2][4];
#pragma unroll
    for (int i = 0; i < 4; i++)
#pragma unroll
        for (int j = 0; j < 2; j++)
#pragma unroll
            for (int e = 0; e < 4; e++) acc[i][j][e] = 0.f;

    const int nIter = C_ >> 5;   // 24
    issue(0);

    const uint32_t lrow = (uint32_t)(lane & 15);
    const uint32_t lhalf = (uint32_t)(lane >> 4);

    for (int it = 0; it < nIter; ++it) {
        if (it + 1 < nIter) { issue(it + 1); cp_wait<1>(); }
        else                { cp_wait<0>(); }
        __syncthreads();
        const uint32_t sb = sbase + (uint32_t)(it & 1) * G_STAGE;
#pragma unroll
        for (int ks = 0; ks < 2; ++ks) {
            const uint32_t kb = (uint32_t)(ks * 32);
            uint32_t bF[4];
            ldsm4(bF, sb + G_SB + (warp_n * 16 + lrow) * ROWB + lhalf * 16 + kb);
            uint32_t aF[4][4];
#pragma unroll
            for (int i = 0; i < 4; ++i)
                ldsm4(aF[i], sb + G_SA + (warp_m * 64 + i * 16 + lrow) * ROWB + lhalf * 16 + kb);
#pragma unroll
            for (int i = 0; i < 4; ++i) {
                mma_f16(acc[i][0], aF[i], bF[0], bF[2]);
                mma_f16(acc[i][1], aF[i], bF[1], bF[3]);
            }
        }
        __syncthreads();
    }

    const int grp = lane >> 2, t4 = lane & 3;
#pragma unroll
    for (int i = 0; i < 4; ++i) {
#pragma unroll
        for (int j = 0; j < 2; ++j) {
#pragma unroll
            for (int e = 0; e < 4; ++e) {
                const int m = m0 + warp_m * 64 + i * 16 + grp + (e >> 1) * 8;
                const int n = n0 + warp_n * 16 + j * 8 + t4 * 2 + (e & 1);
                if (MODE == 4) {
                    outp[(size_t)m * C_ + n] = 0.5f * acc[i][j][e] + bias[n];
                } else {
                    const float r = acc[i][j][e] + bias[n];
                    const int b = m >> 11, ntok = m & 2047;
                    const int h = n / 96, d = n - h * 96;
                    const int bhh = b * 8 + h;
                    if (MODE == 0) {
                        g_qk[((size_t)bhh * N_ + ntok) * D_ + d] = r;
                        g_q16[((size_t)bhh * N_ + ntok) * DPAD + d] = __float2half(r);
                    } else {
                        g_v[((size_t)bhh * N_ + ntok) * D_ + d] = r;
                        g_vt16[((size_t)bhh * D_ + d) * N_ + ntok] = __float2half(r);
                    }
                }
            }
        }
    }
}

// ===========================================================================
// Fused flash attention, fp16, kv-tile 128 (16 iterations), 2-stage ring.
// Grid (N/128, BH), 256 threads = 8 warps; warp w owns q rows [w*16, w*16+16).
// ===========================================================================
#define FA_ROWK 208                         // 96*2 + 16 pad
#define FA_ROWV 272                         // 128*2 + 16 pad
#define FA_SK   0
#define FA_SV   (128 * FA_ROWK)             // 26624
#define FA_STAGE (FA_SV + 96 * FA_ROWV)     // 52736
#define FA_SMEM (2 * FA_STAGE)              // 105472

__global__ __launch_bounds__(256) void fa16_kernel()
{
    extern __shared__ __align__(128) char sm[];
    const uint32_t sbase = smem_to_u32(sm);
    const int tid = threadIdx.x, wid = tid >> 5, lane = tid & 31;
    const int bh = blockIdx.y;
    const int q0 = blockIdx.x * 128;
    const int g = lane >> 2, t4 = lane & 3;

    const __half* q16  = g_q16  + (size_t)bh * N_ * DPAD;
    const __half* vt16 = g_vt16 + (size_t)bh * D_ * N_;

    // q fragments: 6 k-steps of 16 over d=96
    uint32_t qf[6][4];
    {
        const int r0 = q0 + wid * 16 + g;
#pragma unroll
        for (int ks = 0; ks < 6; ks++) {
            const int c0 = ks * 16 + 2 * t4;
            qf[ks][0] = *(const uint32_t*)(q16 + (size_t)r0 * DPAD + c0);
            qf[ks][1] = *(const uint32_t*)(q16 + (size_t)(r0 + 8) * DPAD + c0);
            qf[ks][2] = *(const uint32_t*)(q16 + (size_t)r0 * DPAD + c0 + 8);
            qf[ks][3] = *(const uint32_t*)(q16 + (size_t)(r0 + 8) * DPAD + c0 + 8);
        }
    }

    float O[12][4];
#pragma unroll
    for (int i = 0; i < 12; i++)
#pragma unroll
        for (int e = 0; e < 4; e++) O[i][e] = 0.f;
    float m0v = -1e30f, m1v = -1e30f, l0v = 0.f, l1v = 0.f;

    auto issue = [&](int it) {
        const uint32_t sb = sbase + (uint32_t)(it & 1) * FA_STAGE;
        const int kb = it * 128;
#pragma unroll
        for (int i = 0; i < 12; i++) {
            const int c = i * 256 + tid;
            if (c < 1536) {          // K tile: 128 rows x 96 fp16 (12 x 16B)
                const int r = c / 12, j = c % 12;
                cp16(sb + FA_SK + r * FA_ROWK + j * 16, q16 + (size_t)(kb + r) * DPAD + j * 8);
            } else {                 // V^T tile: 96 d-rows x 128 kv (16 x 16B)
                const int cc = c - 1536, d = cc >> 4, j = cc & 15;
                cp16(sb + FA_SV + d * FA_ROWV + j * 16, vt16 + (size_t)d * N_ + kb + j * 8);
            }
        }
        cp_commit();
    };

    issue(0);
    const float cst = (float)(0.10206207261596575 * 1.4426950408889634); // scale*log2e
    const uint32_t lrowi = (uint32_t)(lane & 15), lhalf = (uint32_t)(lane >> 4);
    const int nIter = N_ / 128;   // 16

    for (int it = 0; it < nIter; ++it) {
        if (it + 1 < nIter) { issue(it + 1); cp_wait<1>(); }
        else                { cp_wait<0>(); }
        __syncthreads();
        const uint32_t sb = sbase + (uint32_t)(it & 1) * FA_STAGE;

        // ---- scores: S[16 x 128] per warp ----
        float S[16][4];
#pragma unroll
        for (int i = 0; i < 16; i++)
#pragma unroll
            for (int e = 0; e < 4; e++) S[i][e] = 0.f;

#pragma unroll
        for (int ks = 0; ks < 6; ks++) {
#pragma unroll
            for (int u = 0; u < 8; u++) {
                uint32_t bF[4];
                ldsm4(bF, sb + FA_SK + (u * 16 + lrowi) * FA_ROWK + ks * 32 + lhalf * 16);
                mma_f16(S[2*u],   qf[ks], bF[0], bF[2]);
                mma_f16(S[2*u+1], qf[ks], bF[1], bF[3]);
            }
        }

        // ---- online softmax (rows g and g+8) ----
        float c0 = -1e30f, c1 = -1e30f;
#pragma unroll
        for (int i = 0; i < 16; i++) {
            c0 = fmaxf(c0, fmaxf(S[i][0], S[i][1]));
            c1 = fmaxf(c1, fmaxf(S[i][2], S[i][3]));
        }
        c0 = fmaxf(c0, __shfl_xor_sync(0xffffffffu, c0, 1));
        c0 = fmaxf(c0, __shfl_xor_sync(0xffffffffu, c0, 2));
        c1 = fmaxf(c1, __shfl_xor_sync(0xffffffffu, c1, 1));
        c1 = fmaxf(c1, __shfl_xor_sync(0xffffffffu, c1, 2));
        const float m0n = fmaxf(m0v, c0), m1n = fmaxf(m1v, c1);
        const float b0 = m0n * cst, b1 = m1n * cst;
        const float f0 = ex2f(fmaf(m0v, cst, -b0));
        const float f1 = ex2f(fmaf(m1v, cst, -b1));
        m0v = m0n; m1v = m1n;

        float s0 = 0.f, s1 = 0.f;
#pragma unroll
        for (int i = 0; i < 16; i++) {
            S[i][0] = ex2f(fmaf(S[i][0], cst, -b0));
            S[i][1] = ex2f(fmaf(S[i][1], cst, -b0));
            S[i][2] = ex2f(fmaf(S[i][2], cst, -b1));
            S[i][3] = ex2f(fmaf(S[i][3], cst, -b1));
            s0 += S[i][0] + S[i][1];
            s1 += S[i][2] + S[i][3];
        }
        s0 += __shfl_xor_sync(0xffffffffu, s0, 1);
        s0 += __shfl_xor_sync(0xffffffffu, s0, 2);
        s1 += __shfl_xor_sync(0xffffffffu, s1, 1);
        s1 += __shfl_xor_sync(0xffffffffu, s1, 2);
        l0v = l0v * f0 + s0;
        l1v = l1v * f1 + s1;

#pragma unroll
        for (int i = 0; i < 12; i++) {
            O[i][0] *= f0; O[i][1] *= f0; O[i][2] *= f1; O[i][3] *= f1;
        }

        // ---- P fragments (C layout == A layout for m16n8k16) ----
        uint32_t pf[8][4];
#pragma unroll
        for (int j = 0; j < 8; j++) {
            pack_h2(S[2*j][0],   S[2*j][1],   pf[j][0]);
            pack_h2(S[2*j][2],   S[2*j][3],   pf[j][1]);
            pack_h2(S[2*j+1][0], S[2*j+1][1], pf[j][2]);
            pack_h2(S[2*j+1][2], S[2*j+1][3], pf[j][3]);
        }

        // ---- O += P @ V ----
#pragma unroll
        for (int j = 0; j < 8; j++) {
#pragma unroll
            for (int u = 0; u < 6; u++) {
                uint32_t bF[4];
                ldsm4(bF, sb + FA_SV + (u * 16 + lrowi) * FA_ROWV + j * 32 + lhalf * 16);
                mma_f16(O[2*u],   pf[j], bF[0], bF[2]);
                mma_f16(O[2*u+1], pf[j], bF[1], bF[3]);
            }
        }
        __syncthreads();
    }

    // ---- epilogue: out1 = O / l -> g_s ----
    const int b = bh >> 3, h = bh & 7;
    const float inv0 = 1.f / l0v, inv1 = 1.f / l1v;
    const int r0 = q0 + wid * 16 + g;
    float* d0 = g_s + (size_t)(b * N_ + r0) * C_ + h * 96;
    float* d1 = g_s + (size_t)(b * N_ + r0 + 8) * C_ + h * 96;
#pragma unroll
    for (int i = 0; i < 12; i++) {
        d0[i * 8 + 2 * t4]     = O[i][0] * inv0;
        d0[i * 8 + 2 * t4 + 1] = O[i][1] * inv0;
        d1[i * 8 + 2 * t4]     = O[i][2] * inv1;
        d1[i * 8 + 2 * t4 + 1] = O[i][3] * inv1;
    }
}

// ===========================================================================
// Branch 2: per-token projected channel attention.
// Reads g_s (out1), adds x_ca, writes g_s16 = fp16(out1 + x_ca).
// ===========================================================================
__global__ __launch_bounds__(128) void branch2_kernel(
    const float* __restrict__ We, const float* __restrict__ be,
    const float* __restrict__ Wf, const float* __restrict__ bf)
{
    __shared__ float sQ[768];
    __shared__ float sV[768];
    __shared__ float sKp[256];
    __shared__ float sVp[256];
    __shared__ float sA[32 * 96];

    const int t = threadIdx.x;
    const size_t tok = blockIdx.x;
    const int b = (int)(tok >> 11), ntok = (int)(tok & 2047);

    for (int i = t; i < 192; i += 128) {
        const int i4 = i * 4;
        const int h = i4 / 96, d = i4 - h * 96;
        const size_t off = ((size_t)(b * 8 + h) * N_ + ntok) * D_ + d;
        ((float4*)sQ)[i] = *(const float4*)(g_qk + off);
        ((float4*)sV)[i] = *(const float4*)(g_v + off);
    }
    __syncthreads();

    for (int p = t; p < 256; p += 128) {
        const int h = p >> 5, e = p & 31;
        float accK = be[e], accV = bf[e];
        const float* wK = We + e * 96;
        const float* wF = Wf + e * 96;
        const float* qh = sQ + h * 96;
        const float* vh = sV + h * 96;
#pragma unroll 8
        for (int d = 0; d < 96; d++) {
            accK = fmaf(qh[d], wK[d], accK);
            accV = fmaf(vh[d], wF[d], accV);
        }
        sKp[e * 8 + h] = accK;
        sVp[h * 32 + e] = accV;
    }
    __syncthreads();

    {
        const int e = t >> 2, qtr = t & 3;
        float a[24];
        float amax = -1e30f;
#pragma unroll
        for (int i = 0; i < 24; i++) {
            const int d = qtr * 24 + i;
            float s = 0.f;
#pragma unroll
            for (int h = 0; h < 8; h++)
                s = fmaf(sKp[e * 8 + h], sQ[h * 96 + d], s);
            a[i] = s;
            amax = fmaxf(amax, s);
        }
        amax = fmaxf(amax, __shfl_xor_sync(0xffffffffu, amax, 1));
        amax = fmaxf(amax, __shfl_xor_sync(0xffffffffu, amax, 2));
        float asum = 0.f;
#pragma unroll
        for (int i = 0; i < 24; i++) { a[i] = __expf(a[i] - amax); asum += a[i]; }
        asum += __shfl_xor_sync(0xffffffffu, asum, 1);
        asum += __shfl_xor_sync(0xffffffffu, asum, 2);
        const float ainv = 1.f / asum;
#pragma unroll
        for (int i = 0; i < 24; i++) sA[e * 96 + qtr * 24 + i] = a[i] * ainv;
    }
    __syncthreads();

    for (int p = t; p < 768; p += 128) {
        const int h = p / 96, d = p - h * 96;
        float s = 0.f;
        const float* vp = sVp + h * 32;
#pragma unroll 8
        for (int e2 = 0; e2 < 32; e2++)
            s = fmaf(vp[e2], sA[e2 * 96 + d], s);
        g_s16[tok * C_ + p] = __float2half(g_s[tok * C_ + p] + s);
    }
}

// ===========================================================================
// Launch
// ===========================================================================
extern "C" void kernel_launch(void* const* d_in, const int* in_sizes, int n_in,
                              void* d_out, int out_size)
{
    const float* x   = (const float*)d_in[0];
    const float* Wqk = (const float*)d_in[1];
    const float* bqk = (const float*)d_in[2];
    const float* Wv  = (const float*)d_in[3];
    const float* bv  = (const float*)d_in[4];
    const float* Wo  = (const float*)d_in[5];
    const float* bo  = (const float*)d_in[6];
    const float* We  = (const float*)d_in[7];
    const float* be  = (const float*)d_in[8];
    const float* Wf  = (const float*)d_in[9];
    const float* bf  = (const float*)d_in[10];
    float* out = (float*)d_out;

    void *p_x16, *p_wqk16, *p_wv16, *p_wo16, *p_s16;
    cudaGetSymbolAddress(&p_x16, g_x16);
    cudaGetSymbolAddress(&p_wqk16, g_Wqk16);
    cudaGetSymbolAddress(&p_wv16, g_Wv16);
    cudaGetSymbolAddress(&p_wo16, g_Wo16);
    cudaGetSymbolAddress(&p_s16, g_s16);

    cudaFuncSetAttribute(gemm16<0>, cudaFuncAttributeMaxDynamicSharedMemorySize, GEMM_SMEM);
    cudaFuncSetAttribute(gemm16<1>, cudaFuncAttributeMaxDynamicSharedMemorySize, GEMM_SMEM);
    cudaFuncSetAttribute(gemm16<4>, cudaFuncAttributeMaxDynamicSharedMemorySize, GEMM_SMEM);
    cudaFuncSetAttribute(fa16_kernel, cudaFuncAttributeMaxDynamicSharedMemorySize, FA_SMEM);

    // 1) converts to fp16: x, Wqk, Wv, Wo
    {
        const int n = TOK * C_;
        half_kernel<<<(n + 255) / 256, 256>>>(x, (__half*)p_x16, n);
        const int nw = C_ * C_;
        half_kernel<<<(nw + 255) / 256, 256>>>(Wqk, (__half*)p_wqk16, nw);
        half_kernel<<<(nw + 255) / 256, 256>>>(Wv,  (__half*)p_wv16,  nw);
        half_kernel<<<(nw + 255) / 256, 256>>>(Wo,  (__half*)p_wo16,  nw);
    }

    // 2) projections (fp16 single-product, M=8192, N=768, K=768)
    dim3 gProj(TOK / 128, C_ / 64);
    gemm16<0><<<gProj, 256, GEMM_SMEM>>>(
        (const __half*)p_x16, (const __half*)p_wqk16, bqk, nullptr);
    gemm16<1><<<gProj, 256, GEMM_SMEM>>>(
        (const __half*)p_x16, (const __half*)p_wv16, bv, nullptr);

    // 3) fused flash attention (fp16, kv-tile 128) -> g_s = out1
    dim3 gFA(N_ / 128, BH_);
    fa16_kernel<<<gFA, 256, FA_SMEM>>>();

    // 4) branch 2: g_s16 = fp16(out1 + x_ca)
    branch2_kernel<<<TOK, 128>>>(We, be, Wf, bf);

    // 5) out = 0.5*(s16 @ Wo16^T) + bo
    gemm16<4><<<gProj, 256, GEMM_SMEM>>>(
        (const __half*)p_s16, (const __half*)p_wo16, bo, out);
}

// round 13
// speedup vs baseline: 9.1646x; 3.1549x over previous
#include <cuda_runtime.h>
#include <cuda_bf16.h>
#include <cuda_fp16.h>
#include <cstdint>

// ===========================================================================
// Problem constants
// ===========================================================================
#define B_   4
#define N_   2048
#define C_   768
#define H_   8
#define D_   96
#define BH_  32            // B*H
#define TOK  8192          // B*N
#define DPAD 128           // head dim padded (stride for q16)

// ===========================================================================
// Device-global scratch (allocation-free rule)
// ===========================================================================
__device__ __align__(256) float g_qk[(size_t)BH_ * N_ * D_];   // fp32 q(=k) [bh][n][d]
__device__ __align__(256) float g_v [(size_t)BH_ * N_ * D_];   // fp32 v     [bh][n][d]
__device__ __align__(256) float g_s [(size_t)TOK * C_];        // out1 (fp32)

__device__ __align__(256) __half g_x16 [(size_t)TOK * C_];
__device__ __align__(256) __half g_Wqk16[C_*C_];
__device__ __align__(256) __half g_Wv16 [C_*C_];
__device__ __align__(256) __half g_Wo16 [C_*C_];
__device__ __align__(256) __half g_q16 [(size_t)BH_ * N_ * DPAD];   // fp16 q, [bh][n][128]
__device__ __align__(256) __half g_vt16[(size_t)BH_ * D_ * N_];     // fp16 v^T, [bh][d][n]
__device__ __align__(256) __half g_s16 [(size_t)TOK * C_];          // out1 + x_ca, fp16

// ===========================================================================
// Asm helpers (base ISA, sm_80+)
// ===========================================================================
__device__ __forceinline__ uint32_t smem_to_u32(const void* p) {
    uint32_t a;
    asm("{ .reg .u64 t; cvta.to.shared.u64 t, %1; cvt.u32.u64 %0, t; }" : "=r"(a) : "l"(p));
    return a;
}
__device__ __forceinline__ void cp16(uint32_t s, const void* g) {
    asm volatile("cp.async.cg.shared.global [%0], [%1], 16;" :: "r"(s), "l"(g));
}
__device__ __forceinline__ void cp_commit() {
    asm volatile("cp.async.commit_group;" ::: "memory");
}
template<int NN> __device__ __forceinline__ void cp_wait() {
    asm volatile("cp.async.wait_group %0;" :: "n"(NN) : "memory");
}
__device__ __forceinline__ void ldsm4(uint32_t (&r)[4], uint32_t addr) {
    asm volatile("ldmatrix.sync.aligned.m8n8.x4.shared.b16 {%0,%1,%2,%3}, [%4];"
                 : "=r"(r[0]), "=r"(r[1]), "=r"(r[2]), "=r"(r[3]) : "r"(addr));
}
__device__ __forceinline__ void mma_f16(float (&d)[4], const uint32_t (&a)[4],
                                        uint32_t b0, uint32_t b1) {
    asm volatile("mma.sync.aligned.m16n8k16.row.col.f32.f16.f16.f32 "
                 "{%0,%1,%2,%3}, {%4,%5,%6,%7}, {%8,%9}, {%0,%1,%2,%3};"
                 : "+f"(d[0]), "+f"(d[1]), "+f"(d[2]), "+f"(d[3])
                 : "r"(a[0]), "r"(a[1]), "r"(a[2]), "r"(a[3]), "r"(b0), "r"(b1));
}
__device__ __forceinline__ float ex2f(float x) {
    float y; asm("ex2.approx.f32 %0, %1;" : "=f"(y) : "f"(x)); return y;
}
__device__ __forceinline__ void pack_h2(float x, float y, uint32_t& r) {
    __half2 h = __float22half2_rn(make_float2(x, y));
    r = *(uint32_t*)&h;
}

// ===========================================================================
// Elementwise convert fp32 -> fp16
// ===========================================================================
__global__ void half_kernel(const float* __restrict__ src,
                            __half* __restrict__ dst, int n)
{
    int i = blockIdx.x * blockDim.x + threadIdx.x;
    if (i < n) dst[i] = __float2half(src[i]);
}

// ===========================================================================
// fp16 single-product GEMM: D[128x64 tile] = A @ B^T + bias (K=768).
// MODE 0: qk-proj, MODE 1: v-proj, MODE 4: out = 0.5*acc + bias.
// ===========================================================================
#define ROWB   80
#define G_SA 0
#define G_SB 10240
#define G_STAGE 15360
#define GEMM_SMEM (2 * G_STAGE)

template<int MODE>
__global__ __launch_bounds__(256, 2) void gemm16(
    const __half* __restrict__ A, const __half* __restrict__ Bw,
    const float* __restrict__ bias, float* __restrict__ outp)
{
    extern __shared__ __align__(128) char sm[];
    const uint32_t sbase = smem_to_u32(sm);
    const int tid  = threadIdx.x;
    const int wid  = tid >> 5, lane = tid & 31;
    const int warp_m = wid >> 2, warp_n = wid & 3;

    const int m0 = blockIdx.x * 128;
    const int n0 = blockIdx.y * 64;

    auto issue = [&](int it) {
        const uint32_t sb = sbase + (uint32_t)(it & 1) * G_STAGE;
        const int k0 = it * 32;
#pragma unroll
        for (int p = 0; p < 2; ++p) {
            const int idx = p * 256 + tid;
            const int r = idx >> 2, j = idx & 3;
            cp16(sb + G_SA + r * ROWB + j * 16, A + (size_t)(m0 + r) * C_ + k0 + j * 8);
        }
        {
            const int r = tid >> 2, j = tid & 3;
            cp16(sb + G_SB + r * ROWB + j * 16, Bw + (size_t)(n0 + r) * C_ + k0 + j * 8);
        }
        cp_commit();
    };

    float acc[4][2][4];
#pragma unroll
    for (int i = 0; i < 4; i++)
#pragma unroll
        for (int j = 0; j < 2; j++)
#pragma unroll
            for (int e = 0; e < 4; e++) acc[i][j][e] = 0.f;

    const int nIter = C_ >> 5;   // 24
    issue(0);

    const uint32_t lrow = (uint32_t)(lane & 15);
    const uint32_t lhalf = (uint32_t)(lane >> 4);

    for (int it = 0; it < nIter; ++it) {
        if (it + 1 < nIter) { issue(it + 1); cp_wait<1>(); }
        else                { cp_wait<0>(); }
        __syncthreads();
        const uint32_t sb = sbase + (uint32_t)(it & 1) * G_STAGE;
#pragma unroll
        for (int ks = 0; ks < 2; ++ks) {
            const uint32_t kb = (uint32_t)(ks * 32);
            uint32_t bF[4];
            ldsm4(bF, sb + G_SB + (warp_n * 16 + lrow) * ROWB + lhalf * 16 + kb);
            uint32_t aF[4][4];
#pragma unroll
            for (int i = 0; i < 4; ++i)
                ldsm4(aF[i], sb + G_SA + (warp_m * 64 + i * 16 + lrow) * ROWB + lhalf * 16 + kb);
#pragma unroll
            for (int i = 0; i < 4; ++i) {
                mma_f16(acc[i][0], aF[i], bF[0], bF[2]);
                mma_f16(acc[i][1], aF[i], bF[1], bF[3]);
            }
        }
        __syncthreads();
    }

    const int grp = lane >> 2, t4 = lane & 3;
#pragma unroll
    for (int i = 0; i < 4; ++i) {
#pragma unroll
        for (int j = 0; j < 2; ++j) {
#pragma unroll
            for (int e = 0; e < 4; ++e) {
                const int m = m0 + warp_m * 64 + i * 16 + grp + (e >> 1) * 8;
                const int n = n0 + warp_n * 16 + j * 8 + t4 * 2 + (e & 1);
                if (MODE == 4) {
                    outp[(size_t)m * C_ + n] = 0.5f * acc[i][j][e] + bias[n];
                } else {
                    const float r = acc[i][j][e] + bias[n];
                    const int b = m >> 11, ntok = m & 2047;
                    const int h = n / 96, d = n - h * 96;
                    const int bhh = b * 8 + h;
                    if (MODE == 0) {
                        g_qk[((size_t)bhh * N_ + ntok) * D_ + d] = r;
                        g_q16[((size_t)bhh * N_ + ntok) * DPAD + d] = __float2half(r);
                    } else {
                        g_v[((size_t)bhh * N_ + ntok) * D_ + d] = r;
                        g_vt16[((size_t)bhh * D_ + d) * N_ + ntok] = __float2half(r);
                    }
                }
            }
        }
    }
}

// ===========================================================================
// Fused flash attention, fp16, kv-tile 128 (16 iterations), 2-stage ring.
// ===========================================================================
#define FA_ROWK 208                         // 96*2 + 16 pad
#define FA_ROWV 272                         // 128*2 + 16 pad
#define FA_SK   0
#define FA_SV   (128 * FA_ROWK)             // 26624
#define FA_STAGE (FA_SV + 96 * FA_ROWV)     // 52736
#define FA_SMEM (2 * FA_STAGE)              // 105472

__global__ __launch_bounds__(256) void fa16_kernel()
{
    extern __shared__ __align__(128) char sm[];
    const uint32_t sbase = smem_to_u32(sm);
    const int tid = threadIdx.x, wid = tid >> 5, lane = tid & 31;
    const int bh = blockIdx.y;
    const int q0 = blockIdx.x * 128;
    const int g = lane >> 2, t4 = lane & 3;

    const __half* q16  = g_q16  + (size_t)bh * N_ * DPAD;
    const __half* vt16 = g_vt16 + (size_t)bh * D_ * N_;

    uint32_t qf[6][4];
    {
        const int r0 = q0 + wid * 16 + g;
#pragma unroll
        for (int ks = 0; ks < 6; ks++) {
            const int c0 = ks * 16 + 2 * t4;
            qf[ks][0] = *(const uint32_t*)(q16 + (size_t)r0 * DPAD + c0);
            qf[ks][1] = *(const uint32_t*)(q16 + (size_t)(r0 + 8) * DPAD + c0);
            qf[ks][2] = *(const uint32_t*)(q16 + (size_t)r0 * DPAD + c0 + 8);
            qf[ks][3] = *(const uint32_t*)(q16 + (size_t)(r0 + 8) * DPAD + c0 + 8);
        }
    }

    float O[12][4];
#pragma unroll
    for (int i = 0; i < 12; i++)
#pragma unroll
        for (int e = 0; e < 4; e++) O[i][e] = 0.f;
    float m0v = -1e30f, m1v = -1e30f, l0v = 0.f, l1v = 0.f;

    auto issue = [&](int it) {
        const uint32_t sb = sbase + (uint32_t)(it & 1) * FA_STAGE;
        const int kb = it * 128;
#pragma unroll
        for (int i = 0; i < 12; i++) {
            const int c = i * 256 + tid;
            if (c < 1536) {
                const int r = c / 12, j = c % 12;
                cp16(sb + FA_SK + r * FA_ROWK + j * 16, q16 + (size_t)(kb + r) * DPAD + j * 8);
            } else {
                const int cc = c - 1536, d = cc >> 4, j = cc & 15;
                cp16(sb + FA_SV + d * FA_ROWV + j * 16, vt16 + (size_t)d * N_ + kb + j * 8);
            }
        }
        cp_commit();
    };

    issue(0);
    const float cst = (float)(0.10206207261596575 * 1.4426950408889634); // scale*log2e
    const uint32_t lrowi = (uint32_t)(lane & 15), lhalf = (uint32_t)(lane >> 4);
    const int nIter = N_ / 128;   // 16

    for (int it = 0; it < nIter; ++it) {
        if (it + 1 < nIter) { issue(it + 1); cp_wait<1>(); }
        else                { cp_wait<0>(); }
        __syncthreads();
        const uint32_t sb = sbase + (uint32_t)(it & 1) * FA_STAGE;

        float S[16][4];
#pragma unroll
        for (int i = 0; i < 16; i++)
#pragma unroll
            for (int e = 0; e < 4; e++) S[i][e] = 0.f;

#pragma unroll
        for (int ks = 0; ks < 6; ks++) {
#pragma unroll
            for (int u = 0; u < 8; u++) {
                uint32_t bF[4];
                ldsm4(bF, sb + FA_SK + (u * 16 + lrowi) * FA_ROWK + ks * 32 + lhalf * 16);
                mma_f16(S[2*u],   qf[ks], bF[0], bF[2]);
                mma_f16(S[2*u+1], qf[ks], bF[1], bF[3]);
            }
        }

        float c0 = -1e30f, c1 = -1e30f;
#pragma unroll
        for (int i = 0; i < 16; i++) {
            c0 = fmaxf(c0, fmaxf(S[i][0], S[i][1]));
            c1 = fmaxf(c1, fmaxf(S[i][2], S[i][3]));
        }
        c0 = fmaxf(c0, __shfl_xor_sync(0xffffffffu, c0, 1));
        c0 = fmaxf(c0, __shfl_xor_sync(0xffffffffu, c0, 2));
        c1 = fmaxf(c1, __shfl_xor_sync(0xffffffffu, c1, 1));
        c1 = fmaxf(c1, __shfl_xor_sync(0xffffffffu, c1, 2));
        const float m0n = fmaxf(m0v, c0), m1n = fmaxf(m1v, c1);
        const float b0 = m0n * cst, b1 = m1n * cst;
        const float f0 = ex2f(fmaf(m0v, cst, -b0));
        const float f1 = ex2f(fmaf(m1v, cst, -b1));
        m0v = m0n; m1v = m1n;

        float s0 = 0.f, s1 = 0.f;
#pragma unroll
        for (int i = 0; i < 16; i++) {
            S[i][0] = ex2f(fmaf(S[i][0], cst, -b0));
            S[i][1] = ex2f(fmaf(S[i][1], cst, -b0));
            S[i][2] = ex2f(fmaf(S[i][2], cst, -b1));
            S[i][3] = ex2f(fmaf(S[i][3], cst, -b1));
            s0 += S[i][0] + S[i][1];
            s1 += S[i][2] + S[i][3];
        }
        s0 += __shfl_xor_sync(0xffffffffu, s0, 1);
        s0 += __shfl_xor_sync(0xffffffffu, s0, 2);
        s1 += __shfl_xor_sync(0xffffffffu, s1, 1);
        s1 += __shfl_xor_sync(0xffffffffu, s1, 2);
        l0v = l0v * f0 + s0;
        l1v = l1v * f1 + s1;

#pragma unroll
        for (int i = 0; i < 12; i++) {
            O[i][0] *= f0; O[i][1] *= f0; O[i][2] *= f1; O[i][3] *= f1;
        }

        uint32_t pf[8][4];
#pragma unroll
        for (int j = 0; j < 8; j++) {
            pack_h2(S[2*j][0],   S[2*j][1],   pf[j][0]);
            pack_h2(S[2*j][2],   S[2*j][3],   pf[j][1]);
            pack_h2(S[2*j+1][0], S[2*j+1][1], pf[j][2]);
            pack_h2(S[2*j+1][2], S[2*j+1][3], pf[j][3]);
        }

#pragma unroll
        for (int j = 0; j < 8; j++) {
#pragma unroll
            for (int u = 0; u < 6; u++) {
                uint32_t bF[4];
                ldsm4(bF, sb + FA_SV + (u * 16 + lrowi) * FA_ROWV + j * 32 + lhalf * 16);
                mma_f16(O[2*u],   pf[j], bF[0], bF[2]);
                mma_f16(O[2*u+1], pf[j], bF[1], bF[3]);
            }
        }
        __syncthreads();
    }

    const int b = bh >> 3, h = bh & 7;
    const float inv0 = 1.f / l0v, inv1 = 1.f / l1v;
    const int r0 = q0 + wid * 16 + g;
    float* d0 = g_s + (size_t)(b * N_ + r0) * C_ + h * 96;
    float* d1 = g_s + (size_t)(b * N_ + r0 + 8) * C_ + h * 96;
#pragma unroll
    for (int i = 0; i < 12; i++) {
        d0[i * 8 + 2 * t4]     = O[i][0] * inv0;
        d0[i * 8 + 2 * t4 + 1] = O[i][1] * inv0;
        d1[i * 8 + 2 * t4]     = O[i][2] * inv1;
        d1[i * 8 + 2 * t4 + 1] = O[i][3] * inv1;
    }
}

// ===========================================================================
// Branch 2 (FIXED memory access): per-token projected channel attention.
// Weights staged in smem transposed [d][e] with pad-33 -> conflict-free
// lane=e access; global weight reads fully coalesced.
// Reads g_s (out1), adds x_ca, writes g_s16 = fp16(out1 + x_ca).
// ===========================================================================
__global__ __launch_bounds__(128) void branch2_kernel(
    const float* __restrict__ We, const float* __restrict__ be,
    const float* __restrict__ Wf, const float* __restrict__ bf)
{
    __shared__ float sQ[768];
    __shared__ float sV[768];
    __shared__ float sWe[96 * 33];   // [d][e], pad 33
    __shared__ float sWf[96 * 33];
    __shared__ float sKp[256];       // [e*8 + h]
    __shared__ float sVp[256];       // [h*32 + e]
    __shared__ float sA[32 * 96];
    __shared__ float sBe[32], sBf[32];

    const int t = threadIdx.x;
    const int wid = t >> 5, lane = t & 31;
    const size_t tok = blockIdx.x;
    const int b = (int)(tok >> 11), ntok = (int)(tok & 2047);

    // Stage weights: coalesced global read, transposed padded smem store.
    for (int i = t; i < 32 * 96; i += 128) {
        const int e = i / 96, d = i - e * 96;
        sWe[d * 33 + e] = We[i];
        sWf[d * 33 + e] = Wf[i];
    }
    if (t < 32) { sBe[t] = be[t]; sBf[t] = bf[t]; }

    // Load q/v rows for this token (per-head layout)
    for (int i = t; i < 192; i += 128) {
        const int i4 = i * 4;
        const int h = i4 / 96, d = i4 - h * 96;
        const size_t off = ((size_t)(b * 8 + h) * N_ + ntok) * D_ + d;
        ((float4*)sQ)[i] = *(const float4*)(g_qk + off);
        ((float4*)sV)[i] = *(const float4*)(g_v + off);
    }
    __syncthreads();

    // k_proj / v_proj: warp wid handles h = 2*wid, 2*wid+1; lane = e.
    // sWe[d*33+lane]: banks (d+lane)%32 -> conflict-free; sQ[h*96+d] broadcast.
#pragma unroll
    for (int hh = 0; hh < 2; hh++) {
        const int h = wid * 2 + hh;
        float accK = sBe[lane], accV = sBf[lane];
        const float* qh = sQ + h * 96;
        const float* vh = sV + h * 96;
#pragma unroll 8
        for (int d = 0; d < 96; d++) {
            const float we = sWe[d * 33 + lane];
            const float wf = sWf[d * 33 + lane];
            accK = fmaf(qh[d], we, accK);
            accV = fmaf(vh[d], wf, accV);
        }
        sKp[lane * 8 + h] = accK;
        sVp[h * 32 + lane] = accV;
    }
    __syncthreads();

    // A[e][d] = softmax_d( sum_h kp[h][e] * q[h][d] )
    {
        const int e = t >> 2, qtr = t & 3;
        float a[24];
        float amax = -1e30f;
#pragma unroll
        for (int i = 0; i < 24; i++) {
            const int d = qtr * 24 + i;
            float s = 0.f;
#pragma unroll
            for (int h = 0; h < 8; h++)
                s = fmaf(sKp[e * 8 + h], sQ[h * 96 + d], s);
            a[i] = s;
            amax = fmaxf(amax, s);
        }
        amax = fmaxf(amax, __shfl_xor_sync(0xffffffffu, amax, 1));
        amax = fmaxf(amax, __shfl_xor_sync(0xffffffffu, amax, 2));
        float asum = 0.f;
#pragma unroll
        for (int i = 0; i < 24; i++) { a[i] = __expf(a[i] - amax); asum += a[i]; }
        asum += __shfl_xor_sync(0xffffffffu, asum, 1);
        asum += __shfl_xor_sync(0xffffffffu, asum, 2);
        const float ainv = 1.f / asum;
#pragma unroll
        for (int i = 0; i < 24; i++) sA[e * 96 + qtr * 24 + i] = a[i] * ainv;
    }
    __syncthreads();

    // x_ca[h][d] = sum_e vp[h][e] * A[e][d]; write fp16(out1 + x_ca)
    for (int p = t; p < 768; p += 128) {
        const int h = p / 96, d = p - h * 96;
        float s = 0.f;
        const float* vp = sVp + h * 32;
#pragma unroll 8
        for (int e2 = 0; e2 < 32; e2++)
            s = fmaf(vp[e2], sA[e2 * 96 + d], s);
        g_s16[tok * C_ + p] = __float2half(g_s[tok * C_ + p] + s);
    }
}

// ===========================================================================
// Launch
// ===========================================================================
extern "C" void kernel_launch(void* const* d_in, const int* in_sizes, int n_in,
                              void* d_out, int out_size)
{
    const float* x   = (const float*)d_in[0];
    const float* Wqk = (const float*)d_in[1];
    const float* bqk = (const float*)d_in[2];
    const float* Wv  = (const float*)d_in[3];
    const float* bv  = (const float*)d_in[4];
    const float* Wo  = (const float*)d_in[5];
    const float* bo  = (const float*)d_in[6];
    const float* We  = (const float*)d_in[7];
    const float* be  = (const float*)d_in[8];
    const float* Wf  = (const float*)d_in[9];
    const float* bf  = (const float*)d_in[10];
    float* out = (float*)d_out;

    void *p_x16, *p_wqk16, *p_wv16, *p_wo16, *p_s16;
    cudaGetSymbolAddress(&p_x16, g_x16);
    cudaGetSymbolAddress(&p_wqk16, g_Wqk16);
    cudaGetSymbolAddress(&p_wv16, g_Wv16);
    cudaGetSymbolAddress(&p_wo16, g_Wo16);
    cudaGetSymbolAddress(&p_s16, g_s16);

    cudaFuncSetAttribute(gemm16<0>, cudaFuncAttributeMaxDynamicSharedMemorySize, GEMM_SMEM);
    cudaFuncSetAttribute(gemm16<1>, cudaFuncAttributeMaxDynamicSharedMemorySize, GEMM_SMEM);
    cudaFuncSetAttribute(gemm16<4>, cudaFuncAttributeMaxDynamicSharedMemorySize, GEMM_SMEM);
    cudaFuncSetAttribute(fa16_kernel, cudaFuncAttributeMaxDynamicSharedMemorySize, FA_SMEM);

    // 1) converts to fp16: x, Wqk, Wv, Wo
    {
        const int n = TOK * C_;
        half_kernel<<<(n + 255) / 256, 256>>>(x, (__half*)p_x16, n);
        const int nw = C_ * C_;
        half_kernel<<<(nw + 255) / 256, 256>>>(Wqk, (__half*)p_wqk16, nw);
        half_kernel<<<(nw + 255) / 256, 256>>>(Wv,  (__half*)p_wv16,  nw);
        half_kernel<<<(nw + 255) / 256, 256>>>(Wo,  (__half*)p_wo16,  nw);
    }

    // 2) projections (fp16 single-product, M=8192, N=768, K=768)
    dim3 gProj(TOK / 128, C_ / 64);
    gemm16<0><<<gProj, 256, GEMM_SMEM>>>(
        (const __half*)p_x16, (const __half*)p_wqk16, bqk, nullptr);
    gemm16<1><<<gProj, 256, GEMM_SMEM>>>(
        (const __half*)p_x16, (const __half*)p_wv16, bv, nullptr);

    // 3) fused flash attention (fp16, kv-tile 128) -> g_s = out1
    dim3 gFA(N_ / 128, BH_);
    fa16_kernel<<<gFA, 256, FA_SMEM>>>();

    // 4) branch 2 (smem-staged weights): g_s16 = fp16(out1 + x_ca)
    branch2_kernel<<<TOK, 128>>>(We, be, Wf, bf);

    // 5) out = 0.5*(s16 @ Wo16^T) + bo
    gemm16<4><<<gProj, 256, GEMM_SMEM>>>(
        (const __half*)p_s16, (const __half*)p_wo16, bo, out);
}